// round 7
// baseline (speedup 1.0000x reference)
#include <cuda_runtime.h>
#include <cuda_bf16.h>
#include <cstdint>

// Problem constants
#define BB 16
#define SS 1024
#define DD 1024
#define HH 16
#define HD 64
#define K3 3072   // gemm split-K: [hi|hi|lo] x [hi|lo|hi]

// Scratch (static __device__ arrays -- no allocations)
__device__ __nv_bfloat16 g_xs[BB * SS * K3];        // ~100 MB
__device__ __nv_bfloat16 g_ws[2048 * K3];           // 12 MB
// Split Q/K, head-major: [(b*16+h)*1024 + s][128] = [qhi(64) | qlo(64)]
__device__ __nv_bfloat16 g_qs[BB * HH * SS * 128];  // 64 MB
__device__ __nv_bfloat16 g_ks[BB * HH * SS * 128];  // 64 MB
// V transposed split: [(bh*2 + hl)*64 + dim][1024 keys]
__device__ __nv_bfloat16 g_vt[BB * HH * 2 * 64 * SS]; // 64 MB

// ---------------------------------------------------------------------------
// PTX helpers (sm_80-level PTX; valid on compute_103)
// ---------------------------------------------------------------------------
__device__ __forceinline__ uint32_t smem_u32(const void* p) {
    uint32_t a;
    asm("{ .reg .u64 t; cvta.to.shared.u64 t, %1; cvt.u32.u64 %0, t; }"
        : "=r"(a) : "l"(p));
    return a;
}
__device__ __forceinline__ void cp16(uint32_t saddr, const void* g) {
    asm volatile("cp.async.cg.shared.global [%0], [%1], 16;" :: "r"(saddr), "l"(g));
}
__device__ __forceinline__ void ldsm_x4(uint32_t& r0, uint32_t& r1, uint32_t& r2,
                                        uint32_t& r3, uint32_t addr) {
    asm volatile("ldmatrix.sync.aligned.m8n8.x4.shared.b16 {%0,%1,%2,%3}, [%4];"
                 : "=r"(r0), "=r"(r1), "=r"(r2), "=r"(r3) : "r"(addr));
}
__device__ __forceinline__ void mma_bf16(float* c, uint32_t a0, uint32_t a1,
                                         uint32_t a2, uint32_t a3,
                                         uint32_t b0, uint32_t b1) {
    asm volatile(
        "mma.sync.aligned.m16n8k16.row.col.f32.bf16.bf16.f32 "
        "{%0,%1,%2,%3}, {%4,%5,%6,%7}, {%8,%9}, {%0,%1,%2,%3};"
        : "+f"(c[0]), "+f"(c[1]), "+f"(c[2]), "+f"(c[3])
        : "r"(a0), "r"(a1), "r"(a2), "r"(a3), "r"(b0), "r"(b1));
}
__device__ __forceinline__ uint32_t sw128(uint32_t byte) {
    return byte ^ ((byte >> 3) & 0x70);
}
__device__ __forceinline__ float ex2f(float x) {
    float y;
    asm("ex2.approx.ftz.f32 %0, %1;" : "=f"(y) : "f"(x));
    return y;
}
__device__ __forceinline__ uint32_t pack_bf2(float a, float b) {
    __nv_bfloat162 h;
    h.x = __float2bfloat16(a);
    h.y = __float2bfloat16(b);
    return *reinterpret_cast<uint32_t*>(&h);
}

// ---------------------------------------------------------------------------
// bf16 split conversion for the projection GEMM
// ---------------------------------------------------------------------------
__global__ void conv_x(const float* __restrict__ X) {
    int i = blockIdx.x * blockDim.x + threadIdx.x;
    if (i >= BB * SS * DD) return;
    int r = i >> 10, c = i & 1023;
    float x = X[i];
    __nv_bfloat16 hi = __float2bfloat16(x);
    __nv_bfloat16 lo = __float2bfloat16(x - __bfloat162float(hi));
    size_t base = (size_t)r * K3;
    g_xs[base + c] = hi;
    g_xs[base + 1024 + c] = hi;
    g_xs[base + 2048 + c] = lo;
}
__global__ void conv_w(const float* __restrict__ W) {
    int i = blockIdx.x * blockDim.x + threadIdx.x;
    if (i >= 2048 * 1024) return;
    int r = i >> 10, c = i & 1023;
    float w = W[i];
    __nv_bfloat16 hi = __float2bfloat16(w);
    __nv_bfloat16 lo = __float2bfloat16(w - __bfloat162float(hi));
    size_t base = (size_t)r * K3;
    g_ws[base + c] = hi;
    g_ws[base + 1024 + c] = lo;
    g_ws[base + 2048 + c] = hi;
}

// V transpose + split: per (kb, h, b) tile of 64 keys x 64 dims
__global__ __launch_bounds__(256) void conv_vt(const float* __restrict__ X) {
    __shared__ float tile[64][65];
    int kb = blockIdx.x, h = blockIdx.y, b = blockIdx.z;
    int tid = threadIdx.x;
#pragma unroll
    for (int i = 0; i < 4; i++) {
        int row = i * 16 + tid / 16;
        int c4 = (tid % 16) * 4;
        float4 v = *(const float4*)&X[((size_t)b * SS + kb * 64 + row) * DD + h * 64 + c4];
        tile[row][c4 + 0] = v.x;
        tile[row][c4 + 1] = v.y;
        tile[row][c4 + 2] = v.z;
        tile[row][c4 + 3] = v.w;
    }
    __syncthreads();
    int bh = b * HH + h;
#pragma unroll
    for (int i = 0; i < 16; i++) {
        int e = tid + i * 256;
        int dim = e >> 6, key = e & 63;
        float x = tile[key][dim];
        __nv_bfloat16 hi = __float2bfloat16(x);
        __nv_bfloat16 lo = __float2bfloat16(x - __bfloat162float(hi));
        g_vt[((size_t)(bh * 2 + 0) * 64 + dim) * SS + kb * 64 + key] = hi;
        g_vt[((size_t)(bh * 2 + 1) * 64 + dim) * SS + kb * 64 + key] = lo;
    }
}

// ---------------------------------------------------------------------------
// HMMA bf16 GEMM (round-5 version: CTA 128x128, warp tile 64x32 -- no spills)
// ---------------------------------------------------------------------------
#define BK 64
#define NSTAGE 3
#define STAGE_BYTES 32768
#define GEMM_SMEM (NSTAGE * STAGE_BYTES)

__global__ __launch_bounds__(256) void gemm_hmma(const float* __restrict__ bias) {
    extern __shared__ char smem[];
    const uint32_t sbase = smem_u32(smem);
    const int tid = threadIdx.x;
    const int lane = tid & 31;
    const int wid = tid >> 5;
    const int warp_m = wid >> 2;
    const int warp_n = wid & 3;
    const int n0 = blockIdx.x * 128;
    const int m0 = blockIdx.y * 128;

    const __nv_bfloat16* gA = g_xs + (size_t)m0 * K3;
    const __nv_bfloat16* gB = g_ws + (size_t)n0 * K3;

    auto load_stage = [&](int kc, int s) {
        uint32_t sA = sbase + s * STAGE_BYTES;
        uint32_t sB = sA + 16384;
        const __nv_bfloat16* a = gA + kc * BK;
        const __nv_bfloat16* b = gB + kc * BK;
#pragma unroll
        for (int i = 0; i < 4; i++) {
            int idx = tid + i * 256;
            int r = idx >> 3, q = idx & 7;
            uint32_t sw = sw128(r * 128 + q * 16);
            cp16(sA + sw, a + (size_t)r * K3 + q * 8);
            cp16(sB + sw, b + (size_t)r * K3 + q * 8);
        }
        asm volatile("cp.async.commit_group;" ::: "memory");
    };

    float acc[4][4][4];
#pragma unroll
    for (int mi = 0; mi < 4; mi++)
#pragma unroll
        for (int nt = 0; nt < 4; nt++)
#pragma unroll
            for (int k = 0; k < 4; k++) acc[mi][nt][k] = 0.0f;

    const int NK = K3 / BK;
    load_stage(0, 0);
    load_stage(1, 1);

    for (int kc = 0; kc < NK; kc++) {
        int s = kc % NSTAGE;
        if (kc + 1 < NK) asm volatile("cp.async.wait_group 1;" ::: "memory");
        else             asm volatile("cp.async.wait_group 0;" ::: "memory");
        __syncthreads();
        if (kc + 2 < NK) load_stage(kc + 2, (kc + 2) % NSTAGE);

        uint32_t sA = sbase + s * STAGE_BYTES;
        uint32_t sB = sA + 16384;

#pragma unroll
        for (int kk = 0; kk < BK / 16; kk++) {
            uint32_t a[4][4], bfr[2][4];
            int colb = kk * 32 + ((lane >> 4) << 4);
#pragma unroll
            for (int mi = 0; mi < 4; mi++) {
                int row = warp_m * 64 + mi * 16 + (lane & 15);
                ldsm_x4(a[mi][0], a[mi][1], a[mi][2], a[mi][3],
                        sA + sw128(row * 128 + colb));
            }
#pragma unroll
            for (int p = 0; p < 2; p++) {
                int row = warp_n * 32 + p * 16 + (lane & 15);
                ldsm_x4(bfr[p][0], bfr[p][1], bfr[p][2], bfr[p][3],
                        sB + sw128(row * 128 + colb));
            }
#pragma unroll
            for (int mi = 0; mi < 4; mi++) {
#pragma unroll
                for (int p = 0; p < 2; p++) {
                    mma_bf16(acc[mi][p * 2 + 0], a[mi][0], a[mi][1], a[mi][2], a[mi][3],
                             bfr[p][0], bfr[p][2]);
                    mma_bf16(acc[mi][p * 2 + 1], a[mi][0], a[mi][1], a[mi][2], a[mi][3],
                             bfr[p][1], bfr[p][3]);
                }
            }
        }
        __syncthreads();
    }

    // Epilogue: bias, scale (q only), bf16 split, head-major store
    const float QSCALE = 0.18033688011112042f;  // 0.125 * log2(e)
    float scale = (n0 < 1024) ? QSCALE : 1.0f;
    __nv_bfloat16* dst = (n0 < 1024) ? g_qs : g_ks;

#pragma unroll
    for (int mi = 0; mi < 4; mi++) {
#pragma unroll
        for (int nt = 0; nt < 4; nt++) {
            int c = warp_n * 32 + nt * 8 + (lane & 3) * 2;
            int nn = (n0 + c) & 1023;
            int hh_ = nn >> 6, d = nn & 63;
            float b0 = __ldg(&bias[n0 + c]);
            float b1 = __ldg(&bias[n0 + c + 1]);
#pragma unroll
            for (int rr = 0; rr < 2; rr++) {
                int r = m0 + warp_m * 64 + mi * 16 + (lane >> 2) + rr * 8;
                int bb = r >> 10, s2 = r & 1023;
                size_t base = ((size_t)(bb * HH + hh_) * SS + s2) * 128;
                float v0 = (acc[mi][nt][rr * 2 + 0] + b0) * scale;
                float v1 = (acc[mi][nt][rr * 2 + 1] + b1) * scale;
                __nv_bfloat16 h0 = __float2bfloat16(v0);
                __nv_bfloat16 h1 = __float2bfloat16(v1);
                __nv_bfloat162 hh, ll;
                hh.x = h0; hh.y = h1;
                ll.x = __float2bfloat16(v0 - __bfloat162float(h0));
                ll.y = __float2bfloat16(v1 - __bfloat162float(h1));
                *(__nv_bfloat162*)&dst[base + d] = hh;
                *(__nv_bfloat162*)&dst[base + 64 + d] = ll;
            }
        }
    }
}

// ---------------------------------------------------------------------------
// HMMA flash attention. CTA = (qb: 128 rows, h, b). 8 warps x 16 q-rows.
// BN=64 keys/iter, 2-stage cp.async. 3-term split on QK and PV.
// R7: Q fragments preloaded once (loop-invariant); khi/vhi fragments loaded
// once and fed to both of their MMA passes. Halves LDSM traffic per iter.
// ---------------------------------------------------------------------------
#define ATT_SMEM (32768 + 2 * 32768)  // Q tiles + 2 stages = 96 KB

__global__ __launch_bounds__(256) void attn_tc(float* __restrict__ Out) {
    extern __shared__ char smem[];
    const uint32_t sb = smem_u32(smem);
    const int tid = threadIdx.x;
    const int lane = tid & 31;
    const int wid = tid >> 5;
    const int qb = blockIdx.x, h = blockIdx.y, b = blockIdx.z;
    const int bh = b * HH + h;

    const uint32_t QHI = sb, QLO = sb + 16384;
    auto STAGE = [&](int s) { return sb + 32768 + s * 32768; };

    // Load Q tiles (128 rows x [hi64|lo64])
    {
        const __nv_bfloat16* qsrc = g_qs + ((size_t)bh * SS + qb * 128) * 128;
#pragma unroll
        for (int i = 0; i < 4; i++) {
            int e = tid + i * 256;
            int row = e >> 3, q = e & 7;
            uint32_t sw = sw128(row * 128 + q * 16);
            cp16(QHI + sw, qsrc + (size_t)row * 128 + q * 8);
            cp16(QLO + sw, qsrc + (size_t)row * 128 + 64 + q * 8);
        }
        asm volatile("cp.async.commit_group;" ::: "memory");
    }

    auto load_kv = [&](int kb, int s) {
        uint32_t st = STAGE(s);
        const __nv_bfloat16* ks = g_ks + ((size_t)bh * SS + kb * 64) * 128;
        const __nv_bfloat16* vh = g_vt + (size_t)(bh * 2 + 0) * 64 * SS + kb * 64;
        const __nv_bfloat16* vl = g_vt + (size_t)(bh * 2 + 1) * 64 * SS + kb * 64;
#pragma unroll
        for (int i = 0; i < 2; i++) {
            int e = tid + i * 256;
            int row = e >> 3, q = e & 7;
            uint32_t sw = sw128(row * 128 + q * 16);
            cp16(st + sw, ks + (size_t)row * 128 + q * 8);
            cp16(st + 8192 + sw, ks + (size_t)row * 128 + 64 + q * 8);
            cp16(st + 16384 + sw, vh + (size_t)row * SS + q * 8);
            cp16(st + 24576 + sw, vl + (size_t)row * SS + q * 8);
        }
        asm volatile("cp.async.commit_group;" ::: "memory");
    };

    load_kv(0, 0);
    load_kv(1, 1);

    // Preload Q fragments (loop-invariant): wait for Q group only (2 pending).
    asm volatile("cp.async.wait_group 2;" ::: "memory");
    __syncthreads();
    uint32_t qh[4][4], ql[4][4];
    {
        int row = wid * 16 + (lane & 15);
#pragma unroll
        for (int kk = 0; kk < 4; kk++) {
            int colb = kk * 32 + ((lane >> 4) << 4);
            ldsm_x4(qh[kk][0], qh[kk][1], qh[kk][2], qh[kk][3],
                    QHI + sw128(row * 128 + colb));
            ldsm_x4(ql[kk][0], ql[kk][1], ql[kk][2], ql[kk][3],
                    QLO + sw128(row * 128 + colb));
        }
    }

    float oacc[8][4];
#pragma unroll
    for (int t = 0; t < 8; t++)
#pragma unroll
        for (int k = 0; k < 4; k++) oacc[t][k] = 0.0f;
    float m0 = -1e30f, m1 = -1e30f, l0 = 0.0f, l1 = 0.0f;

    const int NIT = SS / 64;  // 16
    for (int kb = 0; kb < NIT; kb++) {
        int s = kb & 1;
        if (kb + 1 < NIT) asm volatile("cp.async.wait_group 1;" ::: "memory");
        else              asm volatile("cp.async.wait_group 0;" ::: "memory");
        __syncthreads();

        uint32_t st = STAGE(s);

        // ---- S = qhi*khi + qhi*klo + qlo*khi (khi frags loaded once) ----
        float sacc[8][4];
#pragma unroll
        for (int t = 0; t < 8; t++)
#pragma unroll
            for (int k = 0; k < 4; k++) sacc[t][k] = 0.0f;

#pragma unroll
        for (int kk = 0; kk < 4; kk++) {
            int colb = kk * 32 + ((lane >> 4) << 4);
#pragma unroll
            for (int p = 0; p < 4; p++) {
                int row = p * 16 + (lane & 15);
                uint32_t r0, r1, r2, r3;
                ldsm_x4(r0, r1, r2, r3, st + sw128(row * 128 + colb));  // khi
                mma_bf16(sacc[2 * p + 0], qh[kk][0], qh[kk][1], qh[kk][2], qh[kk][3], r0, r2);
                mma_bf16(sacc[2 * p + 1], qh[kk][0], qh[kk][1], qh[kk][2], qh[kk][3], r1, r3);
                mma_bf16(sacc[2 * p + 0], ql[kk][0], ql[kk][1], ql[kk][2], ql[kk][3], r0, r2);
                mma_bf16(sacc[2 * p + 1], ql[kk][0], ql[kk][1], ql[kk][2], ql[kk][3], r1, r3);
                uint32_t s0, s1, s2, s3;
                ldsm_x4(s0, s1, s2, s3, st + 8192 + sw128(row * 128 + colb));  // klo
                mma_bf16(sacc[2 * p + 0], qh[kk][0], qh[kk][1], qh[kk][2], qh[kk][3], s0, s2);
                mma_bf16(sacc[2 * p + 1], qh[kk][0], qh[kk][1], qh[kk][2], qh[kk][3], s1, s3);
            }
        }

        // ---- online softmax (log2 domain) ----
        float mx0 = -1e30f, mx1 = -1e30f;
#pragma unroll
        for (int t = 0; t < 8; t++) {
            mx0 = fmaxf(mx0, fmaxf(sacc[t][0], sacc[t][1]));
            mx1 = fmaxf(mx1, fmaxf(sacc[t][2], sacc[t][3]));
        }
        mx0 = fmaxf(mx0, __shfl_xor_sync(0xffffffffu, mx0, 1));
        mx0 = fmaxf(mx0, __shfl_xor_sync(0xffffffffu, mx0, 2));
        mx1 = fmaxf(mx1, __shfl_xor_sync(0xffffffffu, mx1, 1));
        mx1 = fmaxf(mx1, __shfl_xor_sync(0xffffffffu, mx1, 2));
        float mn0 = fmaxf(m0, mx0), mn1 = fmaxf(m1, mx1);
        float c0 = ex2f(m0 - mn0), c1 = ex2f(m1 - mn1);
        m0 = mn0; m1 = mn1;

        uint32_t pa_hi[4][4], pa_lo[4][4];
        float sum0 = 0.0f, sum1 = 0.0f;
#pragma unroll
        for (int t = 0; t < 8; t++) {
            float p0 = ex2f(sacc[t][0] - mn0);
            float p1 = ex2f(sacc[t][1] - mn0);
            float p2 = ex2f(sacc[t][2] - mn1);
            float p3 = ex2f(sacc[t][3] - mn1);
            sum0 += p0 + p1;
            sum1 += p2 + p3;
            __nv_bfloat16 h0 = __float2bfloat16(p0), h1 = __float2bfloat16(p1);
            __nv_bfloat16 h2 = __float2bfloat16(p2), h3 = __float2bfloat16(p3);
            int kk = t >> 1, o = (t & 1) * 2;
            {
                __nv_bfloat162 u; u.x = h0; u.y = h1;
                pa_hi[kk][o + 0] = *reinterpret_cast<uint32_t*>(&u);
            }
            {
                __nv_bfloat162 u; u.x = h2; u.y = h3;
                pa_hi[kk][o + 1] = *reinterpret_cast<uint32_t*>(&u);
            }
            pa_lo[kk][o + 0] = pack_bf2(p0 - __bfloat162float(h0),
                                        p1 - __bfloat162float(h1));
            pa_lo[kk][o + 1] = pack_bf2(p2 - __bfloat162float(h2),
                                        p3 - __bfloat162float(h3));
        }
        sum0 += __shfl_xor_sync(0xffffffffu, sum0, 1);
        sum0 += __shfl_xor_sync(0xffffffffu, sum0, 2);
        sum1 += __shfl_xor_sync(0xffffffffu, sum1, 1);
        sum1 += __shfl_xor_sync(0xffffffffu, sum1, 2);
        l0 = l0 * c0 + sum0;
        l1 = l1 * c1 + sum1;
#pragma unroll
        for (int t = 0; t < 8; t++) {
            oacc[t][0] *= c0; oacc[t][1] *= c0;
            oacc[t][2] *= c1; oacc[t][3] *= c1;
        }

        // ---- O += phi*vhi + phi*vlo + plo*vhi (vhi frags loaded once) ----
#pragma unroll
        for (int kk = 0; kk < 4; kk++) {
            int colb = kk * 32 + ((lane >> 4) << 4);
#pragma unroll
            for (int dt = 0; dt < 4; dt++) {
                int row = dt * 16 + (lane & 15);
                uint32_t r0, r1, r2, r3;
                ldsm_x4(r0, r1, r2, r3, st + 16384 + sw128(row * 128 + colb));  // vhi
                mma_bf16(oacc[2 * dt + 0], pa_hi[kk][0], pa_hi[kk][1], pa_hi[kk][2],
                         pa_hi[kk][3], r0, r2);
                mma_bf16(oacc[2 * dt + 1], pa_hi[kk][0], pa_hi[kk][1], pa_hi[kk][2],
                         pa_hi[kk][3], r1, r3);
                mma_bf16(oacc[2 * dt + 0], pa_lo[kk][0], pa_lo[kk][1], pa_lo[kk][2],
                         pa_lo[kk][3], r0, r2);
                mma_bf16(oacc[2 * dt + 1], pa_lo[kk][0], pa_lo[kk][1], pa_lo[kk][2],
                         pa_lo[kk][3], r1, r3);
                uint32_t s0, s1, s2, s3;
                ldsm_x4(s0, s1, s2, s3, st + 24576 + sw128(row * 128 + colb));  // vlo
                mma_bf16(oacc[2 * dt + 0], pa_hi[kk][0], pa_hi[kk][1], pa_hi[kk][2],
                         pa_hi[kk][3], s0, s2);
                mma_bf16(oacc[2 * dt + 1], pa_hi[kk][0], pa_hi[kk][1], pa_hi[kk][2],
                         pa_hi[kk][3], s1, s3);
            }
        }

        __syncthreads();
        if (kb + 2 < NIT) load_kv(kb + 2, s);
    }

    // ---- epilogue ----
    float inv0 = 1.0f / l0, inv1 = 1.0f / l1;
    int r_g0 = qb * 128 + wid * 16 + (lane >> 2);
#pragma unroll
    for (int t = 0; t < 8; t++) {
        int col = h * 64 + t * 8 + (lane & 3) * 2;
        float2 v0 = make_float2(oacc[t][0] * inv0, oacc[t][1] * inv0);
        float2 v1 = make_float2(oacc[t][2] * inv1, oacc[t][3] * inv1);
        *(float2*)&Out[((size_t)b * SS + r_g0) * DD + col] = v0;
        *(float2*)&Out[((size_t)b * SS + r_g0 + 8) * DD + col] = v1;
    }
}

extern "C" void kernel_launch(void* const* d_in, const int* in_sizes, int n_in,
                              void* d_out, int out_size) {
    const float* X = (const float*)d_in[0];     // [16,1024,1024]
    const float* W = (const float*)d_in[1];     // [2048,1024]
    const float* bias = (const float*)d_in[2];  // [2048]
    float* Out = (float*)d_out;                 // [16,1024,1024]

    cudaFuncSetAttribute(gemm_hmma, cudaFuncAttributeMaxDynamicSharedMemorySize,
                         GEMM_SMEM);
    cudaFuncSetAttribute(attn_tc, cudaFuncAttributeMaxDynamicSharedMemorySize,
                         ATT_SMEM);

    conv_x<<<(BB * SS * DD + 255) / 256, 256>>>(X);
    conv_w<<<(2048 * 1024 + 255) / 256, 256>>>(W);
    conv_vt<<<dim3(16, HH, BB), 256>>>(X);
    gemm_hmma<<<dim3(16, 128), 256, GEMM_SMEM>>>(bias);

    attn_tc<<<dim3(SS / 128, HH, BB), 256, ATT_SMEM>>>(Out);
}

// round 8
// speedup vs baseline: 1.4923x; 1.4923x over previous
#include <cuda_runtime.h>
#include <cuda_bf16.h>
#include <cstdint>

// Problem constants
#define BB 16
#define SS 1024
#define DD 1024
#define HH 16
#define HD 64
#define K2 2048   // split storage: [hi(1024) | lo(1024)]

// Scratch (static __device__ arrays -- no allocations)
__device__ __nv_bfloat16 g_xs[BB * SS * K2];        // 64 MB
__device__ __nv_bfloat16 g_ws[2048 * K2];           // 8 MB
// Split Q/K, head-major: [(b*16+h)*1024 + s][128] = [qhi(64) | qlo(64)]
__device__ __nv_bfloat16 g_qs[BB * HH * SS * 128];  // 64 MB
__device__ __nv_bfloat16 g_ks[BB * HH * SS * 128];  // 64 MB
// V transposed split: [(bh*2 + hl)*64 + dim][1024 keys]
__device__ __nv_bfloat16 g_vt[BB * HH * 2 * 64 * SS]; // 64 MB

// ---------------------------------------------------------------------------
// PTX helpers (sm_80-level PTX; valid on compute_103)
// ---------------------------------------------------------------------------
__device__ __forceinline__ uint32_t smem_u32(const void* p) {
    uint32_t a;
    asm("{ .reg .u64 t; cvta.to.shared.u64 t, %1; cvt.u32.u64 %0, t; }"
        : "=r"(a) : "l"(p));
    return a;
}
__device__ __forceinline__ void cp16(uint32_t saddr, const void* g) {
    asm volatile("cp.async.cg.shared.global [%0], [%1], 16;" :: "r"(saddr), "l"(g));
}
__device__ __forceinline__ void ldsm_x4(uint32_t& r0, uint32_t& r1, uint32_t& r2,
                                        uint32_t& r3, uint32_t addr) {
    asm volatile("ldmatrix.sync.aligned.m8n8.x4.shared.b16 {%0,%1,%2,%3}, [%4];"
                 : "=r"(r0), "=r"(r1), "=r"(r2), "=r"(r3) : "r"(addr));
}
__device__ __forceinline__ void mma_bf16(float* c, uint32_t a0, uint32_t a1,
                                         uint32_t a2, uint32_t a3,
                                         uint32_t b0, uint32_t b1) {
    asm volatile(
        "mma.sync.aligned.m16n8k16.row.col.f32.bf16.bf16.f32 "
        "{%0,%1,%2,%3}, {%4,%5,%6,%7}, {%8,%9}, {%0,%1,%2,%3};"
        : "+f"(c[0]), "+f"(c[1]), "+f"(c[2]), "+f"(c[3])
        : "r"(a0), "r"(a1), "r"(a2), "r"(a3), "r"(b0), "r"(b1));
}
__device__ __forceinline__ uint32_t sw128(uint32_t byte) {
    return byte ^ ((byte >> 3) & 0x70);
}
__device__ __forceinline__ float ex2f(float x) {
    float y;
    asm("ex2.approx.ftz.f32 %0, %1;" : "=f"(y) : "f"(x));
    return y;
}
__device__ __forceinline__ uint32_t pack_bf2(float a, float b) {
    __nv_bfloat162 h;
    h.x = __float2bfloat16(a);
    h.y = __float2bfloat16(b);
    return *reinterpret_cast<uint32_t*>(&h);
}

// ---------------------------------------------------------------------------
// bf16 split conversion: row = [hi(1024) | lo(1024)]
// ---------------------------------------------------------------------------
__global__ void conv_x(const float* __restrict__ X) {
    int i = blockIdx.x * blockDim.x + threadIdx.x;
    if (i >= BB * SS * DD) return;
    int r = i >> 10, c = i & 1023;
    float x = X[i];
    __nv_bfloat16 hi = __float2bfloat16(x);
    __nv_bfloat16 lo = __float2bfloat16(x - __bfloat162float(hi));
    size_t base = (size_t)r * K2;
    g_xs[base + c] = hi;
    g_xs[base + 1024 + c] = lo;
}
__global__ void conv_w(const float* __restrict__ W) {
    int i = blockIdx.x * blockDim.x + threadIdx.x;
    if (i >= 2048 * 1024) return;
    int r = i >> 10, c = i & 1023;
    float w = W[i];
    __nv_bfloat16 hi = __float2bfloat16(w);
    __nv_bfloat16 lo = __float2bfloat16(w - __bfloat162float(hi));
    size_t base = (size_t)r * K2;
    g_ws[base + c] = hi;
    g_ws[base + 1024 + c] = lo;
}

// V transpose + split: per (kb, h, b) tile of 64 keys x 64 dims
__global__ __launch_bounds__(256) void conv_vt(const float* __restrict__ X) {
    __shared__ float tile[64][65];
    int kb = blockIdx.x, h = blockIdx.y, b = blockIdx.z;
    int tid = threadIdx.x;
#pragma unroll
    for (int i = 0; i < 4; i++) {
        int row = i * 16 + tid / 16;
        int c4 = (tid % 16) * 4;
        float4 v = *(const float4*)&X[((size_t)b * SS + kb * 64 + row) * DD + h * 64 + c4];
        tile[row][c4 + 0] = v.x;
        tile[row][c4 + 1] = v.y;
        tile[row][c4 + 2] = v.z;
        tile[row][c4 + 3] = v.w;
    }
    __syncthreads();
    int bh = b * HH + h;
#pragma unroll
    for (int i = 0; i < 16; i++) {
        int e = tid + i * 256;
        int dim = e >> 6, key = e & 63;
        float x = tile[key][dim];
        __nv_bfloat16 hi = __float2bfloat16(x);
        __nv_bfloat16 lo = __float2bfloat16(x - __bfloat162float(hi));
        g_vt[((size_t)(bh * 2 + 0) * 64 + dim) * SS + kb * 64 + key] = hi;
        g_vt[((size_t)(bh * 2 + 1) * 64 + dim) * SS + kb * 64 + key] = lo;
    }
}

// ---------------------------------------------------------------------------
// HMMA bf16 GEMM, 3-term split with hi-fragment reuse.
// C[16384, 2048] = X @ W^T + bias  via  ah*bh + ah*bl + al*bh  (K=1024 real).
// CTA 128x128, 8 warps (2x4), warp tile 64x32. Per iter: 32 hi-cols + 32
// lo-cols staged as 128B rows [hi64B | lo64B]. 3-stage cp.async, 1 sync/iter.
// ---------------------------------------------------------------------------
#define BKH 32                         // hi K-cols per iteration
#define NSTAGE 3
#define STAGE_BYTES 32768              // A 16KB + B 16KB
#define GEMM_SMEM (NSTAGE * STAGE_BYTES)

__global__ __launch_bounds__(256, 2) void gemm_hmma(const float* __restrict__ bias) {
    extern __shared__ char smem[];
    const uint32_t sbase = smem_u32(smem);
    const int tid = threadIdx.x;
    const int lane = tid & 31;
    const int wid = tid >> 5;
    const int warp_m = wid >> 2;        // 0..1
    const int warp_n = wid & 3;         // 0..3
    const int n0 = blockIdx.x * 128;
    const int m0 = blockIdx.y * 128;

    const __nv_bfloat16* gA = g_xs + (size_t)m0 * K2;
    const __nv_bfloat16* gB = g_ws + (size_t)n0 * K2;

    // Stage row r (128B) = [ hi cols kc*32..+32 (64B) | lo cols kc*32..+32 ].
    auto load_stage = [&](int kc, int s) {
        uint32_t sA = sbase + s * STAGE_BYTES;
        uint32_t sB = sA + 16384;
        const __nv_bfloat16* a = gA + kc * BKH;
        const __nv_bfloat16* b = gB + kc * BKH;
#pragma unroll
        for (int i = 0; i < 4; i++) {
            int idx = tid + i * 256;            // 0..1023
            int r = idx >> 3, q = idx & 7;
            uint32_t sw = sw128(r * 128 + q * 16);
            size_t goff = (size_t)r * K2 + (q >> 2) * 1024 + (q & 3) * 8;
            cp16(sA + sw, a + goff);
            cp16(sB + sw, b + goff);
        }
        asm volatile("cp.async.commit_group;" ::: "memory");
    };

    float acc[4][4][4];
#pragma unroll
    for (int mi = 0; mi < 4; mi++)
#pragma unroll
        for (int nt = 0; nt < 4; nt++)
#pragma unroll
            for (int k = 0; k < 4; k++) acc[mi][nt][k] = 0.0f;

    const int NK = 1024 / BKH;  // 32
    load_stage(0, 0);
    load_stage(1, 1);

    for (int kc = 0; kc < NK; kc++) {
        int s = kc % NSTAGE;
        if (kc + 1 < NK) asm volatile("cp.async.wait_group 1;" ::: "memory");
        else             asm volatile("cp.async.wait_group 0;" ::: "memory");
        __syncthreads();   // data visible to all + all warps done with stage (kc-1)%3
        if (kc + 2 < NK) load_stage(kc + 2, (kc + 2) % NSTAGE);

        uint32_t sA = sbase + s * STAGE_BYTES;
        uint32_t sB = sA + 16384;

#pragma unroll
        for (int kk = 0; kk < 2; kk++) {        // two k16 steps of the hi chunk
            int colh = kk * 32 + ((lane >> 4) << 4);   // hi bytes 0..63
            int coll = 64 + colh;                       // lo bytes 64..127
            uint32_t ah[4][4];
#pragma unroll
            for (int mi = 0; mi < 4; mi++) {
                int row = warp_m * 64 + mi * 16 + (lane & 15);
                ldsm_x4(ah[mi][0], ah[mi][1], ah[mi][2], ah[mi][3],
                        sA + sw128(row * 128 + colh));
            }
            uint32_t bh[2][4], bl[2][4];
#pragma unroll
            for (int p = 0; p < 2; p++) {
                int row = warp_n * 32 + p * 16 + (lane & 15);
                ldsm_x4(bh[p][0], bh[p][1], bh[p][2], bh[p][3],
                        sB + sw128(row * 128 + colh));
                ldsm_x4(bl[p][0], bl[p][1], bl[p][2], bl[p][3],
                        sB + sw128(row * 128 + coll));
            }
            // ah*bh + ah*bl
#pragma unroll
            for (int mi = 0; mi < 4; mi++) {
#pragma unroll
                for (int p = 0; p < 2; p++) {
                    mma_bf16(acc[mi][p * 2 + 0], ah[mi][0], ah[mi][1], ah[mi][2],
                             ah[mi][3], bh[p][0], bh[p][2]);
                    mma_bf16(acc[mi][p * 2 + 1], ah[mi][0], ah[mi][1], ah[mi][2],
                             ah[mi][3], bh[p][1], bh[p][3]);
                    mma_bf16(acc[mi][p * 2 + 0], ah[mi][0], ah[mi][1], ah[mi][2],
                             ah[mi][3], bl[p][0], bl[p][2]);
                    mma_bf16(acc[mi][p * 2 + 1], ah[mi][0], ah[mi][1], ah[mi][2],
                             ah[mi][3], bl[p][1], bl[p][3]);
                }
            }
            // al*bh (al reuses ah's registers after ah dies)
#pragma unroll
            for (int mi = 0; mi < 4; mi++) {
                uint32_t al0, al1, al2, al3;
                int row = warp_m * 64 + mi * 16 + (lane & 15);
                ldsm_x4(al0, al1, al2, al3, sA + sw128(row * 128 + coll));
#pragma unroll
                for (int p = 0; p < 2; p++) {
                    mma_bf16(acc[mi][p * 2 + 0], al0, al1, al2, al3,
                             bh[p][0], bh[p][2]);
                    mma_bf16(acc[mi][p * 2 + 1], al0, al1, al2, al3,
                             bh[p][1], bh[p][3]);
                }
            }
        }
    }
    __syncthreads();

    // Epilogue: bias, scale (q only), bf16 split, head-major store
    const float QSCALE = 0.18033688011112042f;  // 0.125 * log2(e)
    float scale = (n0 < 1024) ? QSCALE : 1.0f;
    __nv_bfloat16* dst = (n0 < 1024) ? g_qs : g_ks;

#pragma unroll
    for (int mi = 0; mi < 4; mi++) {
#pragma unroll
        for (int nt = 0; nt < 4; nt++) {
            int c = warp_n * 32 + nt * 8 + (lane & 3) * 2;
            int nn = (n0 + c) & 1023;
            int hh_ = nn >> 6, d = nn & 63;
            float b0 = __ldg(&bias[n0 + c]);
            float b1 = __ldg(&bias[n0 + c + 1]);
#pragma unroll
            for (int rr = 0; rr < 2; rr++) {
                int r = m0 + warp_m * 64 + mi * 16 + (lane >> 2) + rr * 8;
                int bb = r >> 10, s2 = r & 1023;
                size_t base = ((size_t)(bb * HH + hh_) * SS + s2) * 128;
                float v0 = (acc[mi][nt][rr * 2 + 0] + b0) * scale;
                float v1 = (acc[mi][nt][rr * 2 + 1] + b1) * scale;
                __nv_bfloat16 h0 = __float2bfloat16(v0);
                __nv_bfloat16 h1 = __float2bfloat16(v1);
                __nv_bfloat162 hh, ll;
                hh.x = h0; hh.y = h1;
                ll.x = __float2bfloat16(v0 - __bfloat162float(h0));
                ll.y = __float2bfloat16(v1 - __bfloat162float(h1));
                *(__nv_bfloat162*)&dst[base + d] = hh;
                *(__nv_bfloat162*)&dst[base + 64 + d] = ll;
            }
        }
    }
}

// ---------------------------------------------------------------------------
// HMMA flash attention (R7 structure: Q frags preloaded; khi/vhi frags reused
// across both of their split passes). CTA = (128 q-rows, h, b), 8 warps.
// ---------------------------------------------------------------------------
#define ATT_SMEM (32768 + 2 * 32768)  // Q tiles + 2 stages = 96 KB

__global__ __launch_bounds__(256) void attn_tc(float* __restrict__ Out) {
    extern __shared__ char smem[];
    const uint32_t sb = smem_u32(smem);
    const int tid = threadIdx.x;
    const int lane = tid & 31;
    const int wid = tid >> 5;
    const int qb = blockIdx.x, h = blockIdx.y, b = blockIdx.z;
    const int bh = b * HH + h;

    const uint32_t QHI = sb, QLO = sb + 16384;
    auto STAGE = [&](int s) { return sb + 32768 + s * 32768; };

    {
        const __nv_bfloat16* qsrc = g_qs + ((size_t)bh * SS + qb * 128) * 128;
#pragma unroll
        for (int i = 0; i < 4; i++) {
            int e = tid + i * 256;
            int row = e >> 3, q = e & 7;
            uint32_t sw = sw128(row * 128 + q * 16);
            cp16(QHI + sw, qsrc + (size_t)row * 128 + q * 8);
            cp16(QLO + sw, qsrc + (size_t)row * 128 + 64 + q * 8);
        }
        asm volatile("cp.async.commit_group;" ::: "memory");
    }

    auto load_kv = [&](int kb, int s) {
        uint32_t st = STAGE(s);
        const __nv_bfloat16* ks = g_ks + ((size_t)bh * SS + kb * 64) * 128;
        const __nv_bfloat16* vh = g_vt + (size_t)(bh * 2 + 0) * 64 * SS + kb * 64;
        const __nv_bfloat16* vl = g_vt + (size_t)(bh * 2 + 1) * 64 * SS + kb * 64;
#pragma unroll
        for (int i = 0; i < 2; i++) {
            int e = tid + i * 256;
            int row = e >> 3, q = e & 7;
            uint32_t sw = sw128(row * 128 + q * 16);
            cp16(st + sw, ks + (size_t)row * 128 + q * 8);
            cp16(st + 8192 + sw, ks + (size_t)row * 128 + 64 + q * 8);
            cp16(st + 16384 + sw, vh + (size_t)row * SS + q * 8);
            cp16(st + 24576 + sw, vl + (size_t)row * SS + q * 8);
        }
        asm volatile("cp.async.commit_group;" ::: "memory");
    };

    load_kv(0, 0);
    load_kv(1, 1);

    // Preload Q fragments (loop-invariant)
    asm volatile("cp.async.wait_group 2;" ::: "memory");
    __syncthreads();
    uint32_t qh[4][4], ql[4][4];
    {
        int row = wid * 16 + (lane & 15);
#pragma unroll
        for (int kk = 0; kk < 4; kk++) {
            int colb = kk * 32 + ((lane >> 4) << 4);
            ldsm_x4(qh[kk][0], qh[kk][1], qh[kk][2], qh[kk][3],
                    QHI + sw128(row * 128 + colb));
            ldsm_x4(ql[kk][0], ql[kk][1], ql[kk][2], ql[kk][3],
                    QLO + sw128(row * 128 + colb));
        }
    }

    float oacc[8][4];
#pragma unroll
    for (int t = 0; t < 8; t++)
#pragma unroll
        for (int k = 0; k < 4; k++) oacc[t][k] = 0.0f;
    float m0 = -1e30f, m1 = -1e30f, l0 = 0.0f, l1 = 0.0f;

    const int NIT = SS / 64;  // 16
    for (int kb = 0; kb < NIT; kb++) {
        int s = kb & 1;
        if (kb + 1 < NIT) asm volatile("cp.async.wait_group 1;" ::: "memory");
        else              asm volatile("cp.async.wait_group 0;" ::: "memory");
        __syncthreads();

        uint32_t st = STAGE(s);

        float sacc[8][4];
#pragma unroll
        for (int t = 0; t < 8; t++)
#pragma unroll
            for (int k = 0; k < 4; k++) sacc[t][k] = 0.0f;

#pragma unroll
        for (int kk = 0; kk < 4; kk++) {
            int colb = kk * 32 + ((lane >> 4) << 4);
#pragma unroll
            for (int p = 0; p < 4; p++) {
                int row = p * 16 + (lane & 15);
                uint32_t r0, r1, r2, r3;
                ldsm_x4(r0, r1, r2, r3, st + sw128(row * 128 + colb));  // khi
                mma_bf16(sacc[2 * p + 0], qh[kk][0], qh[kk][1], qh[kk][2], qh[kk][3], r0, r2);
                mma_bf16(sacc[2 * p + 1], qh[kk][0], qh[kk][1], qh[kk][2], qh[kk][3], r1, r3);
                mma_bf16(sacc[2 * p + 0], ql[kk][0], ql[kk][1], ql[kk][2], ql[kk][3], r0, r2);
                mma_bf16(sacc[2 * p + 1], ql[kk][0], ql[kk][1], ql[kk][2], ql[kk][3], r1, r3);
                uint32_t s0, s1, s2, s3;
                ldsm_x4(s0, s1, s2, s3, st + 8192 + sw128(row * 128 + colb));  // klo
                mma_bf16(sacc[2 * p + 0], qh[kk][0], qh[kk][1], qh[kk][2], qh[kk][3], s0, s2);
                mma_bf16(sacc[2 * p + 1], qh[kk][0], qh[kk][1], qh[kk][2], qh[kk][3], s1, s3);
            }
        }

        float mx0 = -1e30f, mx1 = -1e30f;
#pragma unroll
        for (int t = 0; t < 8; t++) {
            mx0 = fmaxf(mx0, fmaxf(sacc[t][0], sacc[t][1]));
            mx1 = fmaxf(mx1, fmaxf(sacc[t][2], sacc[t][3]));
        }
        mx0 = fmaxf(mx0, __shfl_xor_sync(0xffffffffu, mx0, 1));
        mx0 = fmaxf(mx0, __shfl_xor_sync(0xffffffffu, mx0, 2));
        mx1 = fmaxf(mx1, __shfl_xor_sync(0xffffffffu, mx1, 1));
        mx1 = fmaxf(mx1, __shfl_xor_sync(0xffffffffu, mx1, 2));
        float mn0 = fmaxf(m0, mx0), mn1 = fmaxf(m1, mx1);
        float c0 = ex2f(m0 - mn0), c1 = ex2f(m1 - mn1);
        m0 = mn0; m1 = mn1;

        uint32_t pa_hi[4][4], pa_lo[4][4];
        float sum0 = 0.0f, sum1 = 0.0f;
#pragma unroll
        for (int t = 0; t < 8; t++) {
            float p0 = ex2f(sacc[t][0] - mn0);
            float p1 = ex2f(sacc[t][1] - mn0);
            float p2 = ex2f(sacc[t][2] - mn1);
            float p3 = ex2f(sacc[t][3] - mn1);
            sum0 += p0 + p1;
            sum1 += p2 + p3;
            __nv_bfloat16 h0 = __float2bfloat16(p0), h1 = __float2bfloat16(p1);
            __nv_bfloat16 h2 = __float2bfloat16(p2), h3 = __float2bfloat16(p3);
            int kk = t >> 1, o = (t & 1) * 2;
            {
                __nv_bfloat162 u; u.x = h0; u.y = h1;
                pa_hi[kk][o + 0] = *reinterpret_cast<uint32_t*>(&u);
            }
            {
                __nv_bfloat162 u; u.x = h2; u.y = h3;
                pa_hi[kk][o + 1] = *reinterpret_cast<uint32_t*>(&u);
            }
            pa_lo[kk][o + 0] = pack_bf2(p0 - __bfloat162float(h0),
                                        p1 - __bfloat162float(h1));
            pa_lo[kk][o + 1] = pack_bf2(p2 - __bfloat162float(h2),
                                        p3 - __bfloat162float(h3));
        }
        sum0 += __shfl_xor_sync(0xffffffffu, sum0, 1);
        sum0 += __shfl_xor_sync(0xffffffffu, sum0, 2);
        sum1 += __shfl_xor_sync(0xffffffffu, sum1, 1);
        sum1 += __shfl_xor_sync(0xffffffffu, sum1, 2);
        l0 = l0 * c0 + sum0;
        l1 = l1 * c1 + sum1;
#pragma unroll
        for (int t = 0; t < 8; t++) {
            oacc[t][0] *= c0; oacc[t][1] *= c0;
            oacc[t][2] *= c1; oacc[t][3] *= c1;
        }

#pragma unroll
        for (int kk = 0; kk < 4; kk++) {
            int colb = kk * 32 + ((lane >> 4) << 4);
#pragma unroll
            for (int dt = 0; dt < 4; dt++) {
                int row = dt * 16 + (lane & 15);
                uint32_t r0, r1, r2, r3;
                ldsm_x4(r0, r1, r2, r3, st + 16384 + sw128(row * 128 + colb));  // vhi
                mma_bf16(oacc[2 * dt + 0], pa_hi[kk][0], pa_hi[kk][1], pa_hi[kk][2],
                         pa_hi[kk][3], r0, r2);
                mma_bf16(oacc[2 * dt + 1], pa_hi[kk][0], pa_hi[kk][1], pa_hi[kk][2],
                         pa_hi[kk][3], r1, r3);
                mma_bf16(oacc[2 * dt + 0], pa_lo[kk][0], pa_lo[kk][1], pa_lo[kk][2],
                         pa_lo[kk][3], r0, r2);
                mma_bf16(oacc[2 * dt + 1], pa_lo[kk][0], pa_lo[kk][1], pa_lo[kk][2],
                         pa_lo[kk][3], r1, r3);
                uint32_t s0, s1, s2, s3;
                ldsm_x4(s0, s1, s2, s3, st + 24576 + sw128(row * 128 + colb));  // vlo
                mma_bf16(oacc[2 * dt + 0], pa_hi[kk][0], pa_hi[kk][1], pa_hi[kk][2],
                         pa_hi[kk][3], s0, s2);
                mma_bf16(oacc[2 * dt + 1], pa_hi[kk][0], pa_hi[kk][1], pa_hi[kk][2],
                         pa_hi[kk][3], s1, s3);
            }
        }

        __syncthreads();
        if (kb + 2 < NIT) load_kv(kb + 2, s);
    }

    float inv0 = 1.0f / l0, inv1 = 1.0f / l1;
    int r_g0 = qb * 128 + wid * 16 + (lane >> 2);
#pragma unroll
    for (int t = 0; t < 8; t++) {
        int col = h * 64 + t * 8 + (lane & 3) * 2;
        float2 v0 = make_float2(oacc[t][0] * inv0, oacc[t][1] * inv0);
        float2 v1 = make_float2(oacc[t][2] * inv1, oacc[t][3] * inv1);
        *(float2*)&Out[((size_t)b * SS + r_g0) * DD + col] = v0;
        *(float2*)&Out[((size_t)b * SS + r_g0 + 8) * DD + col] = v1;
    }
}

extern "C" void kernel_launch(void* const* d_in, const int* in_sizes, int n_in,
                              void* d_out, int out_size) {
    const float* X = (const float*)d_in[0];     // [16,1024,1024]
    const float* W = (const float*)d_in[1];     // [2048,1024]
    const float* bias = (const float*)d_in[2];  // [2048]
    float* Out = (float*)d_out;                 // [16,1024,1024]

    cudaFuncSetAttribute(gemm_hmma, cudaFuncAttributeMaxDynamicSharedMemorySize,
                         GEMM_SMEM);
    cudaFuncSetAttribute(attn_tc, cudaFuncAttributeMaxDynamicSharedMemorySize,
                         ATT_SMEM);

    conv_x<<<(BB * SS * DD + 255) / 256, 256>>>(X);
    conv_w<<<(2048 * 1024 + 255) / 256, 256>>>(W);
    conv_vt<<<dim3(16, HH, BB), 256>>>(X);
    gemm_hmma<<<dim3(16, 128), 256, GEMM_SMEM>>>(bias);

    attn_tc<<<dim3(SS / 128, HH, BB), 256, ATT_SMEM>>>(Out);
}

// round 9
// speedup vs baseline: 1.5080x; 1.0105x over previous
#include <cuda_runtime.h>
#include <cuda_bf16.h>
#include <cstdint>

// Problem constants
#define BB 16
#define SS 1024
#define DD 1024
#define HH 16
#define HD 64
#define K2 2048   // split storage: [hi(1024) | lo(1024)]

// Scratch (static __device__ arrays -- no allocations)
__device__ __nv_bfloat16 g_xs[BB * SS * K2];        // 64 MB
__device__ __nv_bfloat16 g_ws[2048 * K2];           // 8 MB
// Split Q/K, head-major: [(b*16+h)*1024 + s][128] = [qhi(64) | qlo(64)]
__device__ __nv_bfloat16 g_qs[BB * HH * SS * 128];  // 64 MB
__device__ __nv_bfloat16 g_ks[BB * HH * SS * 128];  // 64 MB
// V transposed split: [(bh*2 + hl)*64 + dim][1024 keys]
__device__ __nv_bfloat16 g_vt[BB * HH * 2 * 64 * SS]; // 64 MB

// ---------------------------------------------------------------------------
// PTX helpers (sm_80-level PTX; valid on compute_103)
// ---------------------------------------------------------------------------
__device__ __forceinline__ uint32_t smem_u32(const void* p) {
    uint32_t a;
    asm("{ .reg .u64 t; cvta.to.shared.u64 t, %1; cvt.u32.u64 %0, t; }"
        : "=r"(a) : "l"(p));
    return a;
}
__device__ __forceinline__ void cp16(uint32_t saddr, const void* g) {
    asm volatile("cp.async.cg.shared.global [%0], [%1], 16;" :: "r"(saddr), "l"(g));
}
__device__ __forceinline__ void ldsm_x4(uint32_t& r0, uint32_t& r1, uint32_t& r2,
                                        uint32_t& r3, uint32_t addr) {
    asm volatile("ldmatrix.sync.aligned.m8n8.x4.shared.b16 {%0,%1,%2,%3}, [%4];"
                 : "=r"(r0), "=r"(r1), "=r"(r2), "=r"(r3) : "r"(addr));
}
__device__ __forceinline__ void mma_bf16(float* c, uint32_t a0, uint32_t a1,
                                         uint32_t a2, uint32_t a3,
                                         uint32_t b0, uint32_t b1) {
    asm volatile(
        "mma.sync.aligned.m16n8k16.row.col.f32.bf16.bf16.f32 "
        "{%0,%1,%2,%3}, {%4,%5,%6,%7}, {%8,%9}, {%0,%1,%2,%3};"
        : "+f"(c[0]), "+f"(c[1]), "+f"(c[2]), "+f"(c[3])
        : "r"(a0), "r"(a1), "r"(a2), "r"(a3), "r"(b0), "r"(b1));
}
__device__ __forceinline__ uint32_t sw128(uint32_t byte) {
    return byte ^ ((byte >> 3) & 0x70);
}
__device__ __forceinline__ float ex2f(float x) {
    float y;
    asm("ex2.approx.ftz.f32 %0, %1;" : "=f"(y) : "f"(x));
    return y;
}
__device__ __forceinline__ uint32_t pack_bf2(float a, float b) {
    __nv_bfloat162 h;
    h.x = __float2bfloat16(a);
    h.y = __float2bfloat16(b);
    return *reinterpret_cast<uint32_t*>(&h);
}

// ---------------------------------------------------------------------------
// bf16 split conversion: row = [hi(1024) | lo(1024)]
// ---------------------------------------------------------------------------
__global__ void conv_x(const float* __restrict__ X) {
    int i = blockIdx.x * blockDim.x + threadIdx.x;
    if (i >= BB * SS * DD) return;
    int r = i >> 10, c = i & 1023;
    float x = X[i];
    __nv_bfloat16 hi = __float2bfloat16(x);
    __nv_bfloat16 lo = __float2bfloat16(x - __bfloat162float(hi));
    size_t base = (size_t)r * K2;
    g_xs[base + c] = hi;
    g_xs[base + 1024 + c] = lo;
}
__global__ void conv_w(const float* __restrict__ W) {
    int i = blockIdx.x * blockDim.x + threadIdx.x;
    if (i >= 2048 * 1024) return;
    int r = i >> 10, c = i & 1023;
    float w = W[i];
    __nv_bfloat16 hi = __float2bfloat16(w);
    __nv_bfloat16 lo = __float2bfloat16(w - __bfloat162float(hi));
    size_t base = (size_t)r * K2;
    g_ws[base + c] = hi;
    g_ws[base + 1024 + c] = lo;
}

// V transpose + split: per (kb, h, b) tile of 64 keys x 64 dims
__global__ __launch_bounds__(256) void conv_vt(const float* __restrict__ X) {
    __shared__ float tile[64][65];
    int kb = blockIdx.x, h = blockIdx.y, b = blockIdx.z;
    int tid = threadIdx.x;
#pragma unroll
    for (int i = 0; i < 4; i++) {
        int row = i * 16 + tid / 16;
        int c4 = (tid % 16) * 4;
        float4 v = *(const float4*)&X[((size_t)b * SS + kb * 64 + row) * DD + h * 64 + c4];
        tile[row][c4 + 0] = v.x;
        tile[row][c4 + 1] = v.y;
        tile[row][c4 + 2] = v.z;
        tile[row][c4 + 3] = v.w;
    }
    __syncthreads();
    int bh = b * HH + h;
#pragma unroll
    for (int i = 0; i < 16; i++) {
        int e = tid + i * 256;
        int dim = e >> 6, key = e & 63;
        float x = tile[key][dim];
        __nv_bfloat16 hi = __float2bfloat16(x);
        __nv_bfloat16 lo = __float2bfloat16(x - __bfloat162float(hi));
        g_vt[((size_t)(bh * 2 + 0) * 64 + dim) * SS + kb * 64 + key] = hi;
        g_vt[((size_t)(bh * 2 + 1) * 64 + dim) * SS + kb * 64 + key] = lo;
    }
}

// ---------------------------------------------------------------------------
// HMMA bf16 GEMM, 3-term split with hi-fragment reuse.
// R9: CTA 128x64, 8 warps (4x2), warp tile 32x32, 3-stage x 24KB.
// __launch_bounds__(256,3) => ~85 regs, 3 CTAs/SM, occ 37.5% (latency fix).
// ---------------------------------------------------------------------------
#define BKH 32                         // hi K-cols per iteration
#define NSTAGE 3
#define STAGE_BYTES 24576              // A 16KB + B 8KB
#define GEMM_SMEM (NSTAGE * STAGE_BYTES)

__global__ __launch_bounds__(256, 3) void gemm_hmma(const float* __restrict__ bias) {
    extern __shared__ char smem[];
    const uint32_t sbase = smem_u32(smem);
    const int tid = threadIdx.x;
    const int lane = tid & 31;
    const int wid = tid >> 5;
    const int warp_m = wid & 3;         // 0..3  (x32 rows)
    const int warp_n = wid >> 2;        // 0..1  (x32 cols)
    const int n0 = blockIdx.x * 64;
    const int m0 = blockIdx.y * 128;

    const __nv_bfloat16* gA = g_xs + (size_t)m0 * K2;
    const __nv_bfloat16* gB = g_ws + (size_t)n0 * K2;

    // Stage row r (128B) = [ hi cols kc*32..+32 (64B) | lo cols kc*32..+32 ].
    auto load_stage = [&](int kc, int s) {
        uint32_t sA = sbase + s * STAGE_BYTES;
        uint32_t sB = sA + 16384;
        const __nv_bfloat16* a = gA + kc * BKH;
        const __nv_bfloat16* b = gB + kc * BKH;
#pragma unroll
        for (int i = 0; i < 4; i++) {           // A: 1024 x 16B
            int idx = tid + i * 256;
            int r = idx >> 3, q = idx & 7;
            uint32_t sw = sw128(r * 128 + q * 16);
            size_t goff = (size_t)r * K2 + (q >> 2) * 1024 + (q & 3) * 8;
            cp16(sA + sw, a + goff);
        }
#pragma unroll
        for (int i = 0; i < 2; i++) {           // B: 512 x 16B
            int idx = tid + i * 256;
            int r = idx >> 3, q = idx & 7;
            uint32_t sw = sw128(r * 128 + q * 16);
            size_t goff = (size_t)r * K2 + (q >> 2) * 1024 + (q & 3) * 8;
            cp16(sB + sw, b + goff);
        }
        asm volatile("cp.async.commit_group;" ::: "memory");
    };

    float acc[2][4][4];
#pragma unroll
    for (int mi = 0; mi < 2; mi++)
#pragma unroll
        for (int nt = 0; nt < 4; nt++)
#pragma unroll
            for (int k = 0; k < 4; k++) acc[mi][nt][k] = 0.0f;

    const int NK = 1024 / BKH;  // 32
    load_stage(0, 0);
    load_stage(1, 1);

    for (int kc = 0; kc < NK; kc++) {
        int s = kc % NSTAGE;
        if (kc + 1 < NK) asm volatile("cp.async.wait_group 1;" ::: "memory");
        else             asm volatile("cp.async.wait_group 0;" ::: "memory");
        __syncthreads();
        if (kc + 2 < NK) load_stage(kc + 2, (kc + 2) % NSTAGE);

        uint32_t sA = sbase + s * STAGE_BYTES;
        uint32_t sB = sA + 16384;

#pragma unroll
        for (int kk = 0; kk < 2; kk++) {        // two k16 steps
            int colh = kk * 32 + ((lane >> 4) << 4);   // hi bytes 0..63
            int coll = 64 + colh;                       // lo bytes 64..127
            uint32_t ah[2][4];
#pragma unroll
            for (int mi = 0; mi < 2; mi++) {
                int row = warp_m * 32 + mi * 16 + (lane & 15);
                ldsm_x4(ah[mi][0], ah[mi][1], ah[mi][2], ah[mi][3],
                        sA + sw128(row * 128 + colh));
            }
            uint32_t bh[2][4], bl[2][4];
#pragma unroll
            for (int p = 0; p < 2; p++) {
                int row = warp_n * 32 + p * 16 + (lane & 15);
                ldsm_x4(bh[p][0], bh[p][1], bh[p][2], bh[p][3],
                        sB + sw128(row * 128 + colh));
                ldsm_x4(bl[p][0], bl[p][1], bl[p][2], bl[p][3],
                        sB + sw128(row * 128 + coll));
            }
            // ah*bh + ah*bl
#pragma unroll
            for (int mi = 0; mi < 2; mi++) {
#pragma unroll
                for (int p = 0; p < 2; p++) {
                    mma_bf16(acc[mi][p * 2 + 0], ah[mi][0], ah[mi][1], ah[mi][2],
                             ah[mi][3], bh[p][0], bh[p][2]);
                    mma_bf16(acc[mi][p * 2 + 1], ah[mi][0], ah[mi][1], ah[mi][2],
                             ah[mi][3], bh[p][1], bh[p][3]);
                    mma_bf16(acc[mi][p * 2 + 0], ah[mi][0], ah[mi][1], ah[mi][2],
                             ah[mi][3], bl[p][0], bl[p][2]);
                    mma_bf16(acc[mi][p * 2 + 1], ah[mi][0], ah[mi][1], ah[mi][2],
                             ah[mi][3], bl[p][1], bl[p][3]);
                }
            }
            // al*bh (al loaded after ah dies)
#pragma unroll
            for (int mi = 0; mi < 2; mi++) {
                uint32_t al0, al1, al2, al3;
                int row = warp_m * 32 + mi * 16 + (lane & 15);
                ldsm_x4(al0, al1, al2, al3, sA + sw128(row * 128 + coll));
#pragma unroll
                for (int p = 0; p < 2; p++) {
                    mma_bf16(acc[mi][p * 2 + 0], al0, al1, al2, al3,
                             bh[p][0], bh[p][2]);
                    mma_bf16(acc[mi][p * 2 + 1], al0, al1, al2, al3,
                             bh[p][1], bh[p][3]);
                }
            }
        }
    }
    __syncthreads();

    // Epilogue: bias, scale (q only), bf16 split, head-major store
    const float QSCALE = 0.18033688011112042f;  // 0.125 * log2(e)
    float scale = (n0 < 1024) ? QSCALE : 1.0f;
    __nv_bfloat16* dst = (n0 < 1024) ? g_qs : g_ks;

#pragma unroll
    for (int mi = 0; mi < 2; mi++) {
#pragma unroll
        for (int nt = 0; nt < 4; nt++) {
            int c = warp_n * 32 + nt * 8 + (lane & 3) * 2;
            int nn = (n0 + c) & 1023;
            int hh_ = nn >> 6, d = nn & 63;
            float b0 = __ldg(&bias[n0 + c]);
            float b1 = __ldg(&bias[n0 + c + 1]);
#pragma unroll
            for (int rr = 0; rr < 2; rr++) {
                int r = m0 + warp_m * 32 + mi * 16 + (lane >> 2) + rr * 8;
                int bb = r >> 10, s2 = r & 1023;
                size_t base = ((size_t)(bb * HH + hh_) * SS + s2) * 128;
                float v0 = (acc[mi][nt][rr * 2 + 0] + b0) * scale;
                float v1 = (acc[mi][nt][rr * 2 + 1] + b1) * scale;
                __nv_bfloat16 h0 = __float2bfloat16(v0);
                __nv_bfloat16 h1 = __float2bfloat16(v1);
                __nv_bfloat162 hh, ll;
                hh.x = h0; hh.y = h1;
                ll.x = __float2bfloat16(v0 - __bfloat162float(h0));
                ll.y = __float2bfloat16(v1 - __bfloat162float(h1));
                *(__nv_bfloat162*)&dst[base + d] = hh;
                *(__nv_bfloat162*)&dst[base + 64 + d] = ll;
            }
        }
    }
}

// ---------------------------------------------------------------------------
// HMMA flash attention (unchanged from R8)
// ---------------------------------------------------------------------------
#define ATT_SMEM (32768 + 2 * 32768)  // Q tiles + 2 stages = 96 KB

__global__ __launch_bounds__(256) void attn_tc(float* __restrict__ Out) {
    extern __shared__ char smem[];
    const uint32_t sb = smem_u32(smem);
    const int tid = threadIdx.x;
    const int lane = tid & 31;
    const int wid = tid >> 5;
    const int qb = blockIdx.x, h = blockIdx.y, b = blockIdx.z;
    const int bh = b * HH + h;

    const uint32_t QHI = sb, QLO = sb + 16384;
    auto STAGE = [&](int s) { return sb + 32768 + s * 32768; };

    {
        const __nv_bfloat16* qsrc = g_qs + ((size_t)bh * SS + qb * 128) * 128;
#pragma unroll
        for (int i = 0; i < 4; i++) {
            int e = tid + i * 256;
            int row = e >> 3, q = e & 7;
            uint32_t sw = sw128(row * 128 + q * 16);
            cp16(QHI + sw, qsrc + (size_t)row * 128 + q * 8);
            cp16(QLO + sw, qsrc + (size_t)row * 128 + 64 + q * 8);
        }
        asm volatile("cp.async.commit_group;" ::: "memory");
    }

    auto load_kv = [&](int kb, int s) {
        uint32_t st = STAGE(s);
        const __nv_bfloat16* ks = g_ks + ((size_t)bh * SS + kb * 64) * 128;
        const __nv_bfloat16* vh = g_vt + (size_t)(bh * 2 + 0) * 64 * SS + kb * 64;
        const __nv_bfloat16* vl = g_vt + (size_t)(bh * 2 + 1) * 64 * SS + kb * 64;
#pragma unroll
        for (int i = 0; i < 2; i++) {
            int e = tid + i * 256;
            int row = e >> 3, q = e & 7;
            uint32_t sw = sw128(row * 128 + q * 16);
            cp16(st + sw, ks + (size_t)row * 128 + q * 8);
            cp16(st + 8192 + sw, ks + (size_t)row * 128 + 64 + q * 8);
            cp16(st + 16384 + sw, vh + (size_t)row * SS + q * 8);
            cp16(st + 24576 + sw, vl + (size_t)row * SS + q * 8);
        }
        asm volatile("cp.async.commit_group;" ::: "memory");
    };

    load_kv(0, 0);
    load_kv(1, 1);

    asm volatile("cp.async.wait_group 2;" ::: "memory");
    __syncthreads();
    uint32_t qh[4][4], ql[4][4];
    {
        int row = wid * 16 + (lane & 15);
#pragma unroll
        for (int kk = 0; kk < 4; kk++) {
            int colb = kk * 32 + ((lane >> 4) << 4);
            ldsm_x4(qh[kk][0], qh[kk][1], qh[kk][2], qh[kk][3],
                    QHI + sw128(row * 128 + colb));
            ldsm_x4(ql[kk][0], ql[kk][1], ql[kk][2], ql[kk][3],
                    QLO + sw128(row * 128 + colb));
        }
    }

    float oacc[8][4];
#pragma unroll
    for (int t = 0; t < 8; t++)
#pragma unroll
        for (int k = 0; k < 4; k++) oacc[t][k] = 0.0f;
    float m0 = -1e30f, m1 = -1e30f, l0 = 0.0f, l1 = 0.0f;

    const int NIT = SS / 64;  // 16
    for (int kb = 0; kb < NIT; kb++) {
        int s = kb & 1;
        if (kb + 1 < NIT) asm volatile("cp.async.wait_group 1;" ::: "memory");
        else              asm volatile("cp.async.wait_group 0;" ::: "memory");
        __syncthreads();

        uint32_t st = STAGE(s);

        float sacc[8][4];
#pragma unroll
        for (int t = 0; t < 8; t++)
#pragma unroll
            for (int k = 0; k < 4; k++) sacc[t][k] = 0.0f;

#pragma unroll
        for (int kk = 0; kk < 4; kk++) {
            int colb = kk * 32 + ((lane >> 4) << 4);
#pragma unroll
            for (int p = 0; p < 4; p++) {
                int row = p * 16 + (lane & 15);
                uint32_t r0, r1, r2, r3;
                ldsm_x4(r0, r1, r2, r3, st + sw128(row * 128 + colb));  // khi
                mma_bf16(sacc[2 * p + 0], qh[kk][0], qh[kk][1], qh[kk][2], qh[kk][3], r0, r2);
                mma_bf16(sacc[2 * p + 1], qh[kk][0], qh[kk][1], qh[kk][2], qh[kk][3], r1, r3);
                mma_bf16(sacc[2 * p + 0], ql[kk][0], ql[kk][1], ql[kk][2], ql[kk][3], r0, r2);
                mma_bf16(sacc[2 * p + 1], ql[kk][0], ql[kk][1], ql[kk][2], ql[kk][3], r1, r3);
                uint32_t s0, s1, s2, s3;
                ldsm_x4(s0, s1, s2, s3, st + 8192 + sw128(row * 128 + colb));  // klo
                mma_bf16(sacc[2 * p + 0], qh[kk][0], qh[kk][1], qh[kk][2], qh[kk][3], s0, s2);
                mma_bf16(sacc[2 * p + 1], qh[kk][0], qh[kk][1], qh[kk][2], qh[kk][3], s1, s3);
            }
        }

        float mx0 = -1e30f, mx1 = -1e30f;
#pragma unroll
        for (int t = 0; t < 8; t++) {
            mx0 = fmaxf(mx0, fmaxf(sacc[t][0], sacc[t][1]));
            mx1 = fmaxf(mx1, fmaxf(sacc[t][2], sacc[t][3]));
        }
        mx0 = fmaxf(mx0, __shfl_xor_sync(0xffffffffu, mx0, 1));
        mx0 = fmaxf(mx0, __shfl_xor_sync(0xffffffffu, mx0, 2));
        mx1 = fmaxf(mx1, __shfl_xor_sync(0xffffffffu, mx1, 1));
        mx1 = fmaxf(mx1, __shfl_xor_sync(0xffffffffu, mx1, 2));
        float mn0 = fmaxf(m0, mx0), mn1 = fmaxf(m1, mx1);
        float c0 = ex2f(m0 - mn0), c1 = ex2f(m1 - mn1);
        m0 = mn0; m1 = mn1;

        uint32_t pa_hi[4][4], pa_lo[4][4];
        float sum0 = 0.0f, sum1 = 0.0f;
#pragma unroll
        for (int t = 0; t < 8; t++) {
            float p0 = ex2f(sacc[t][0] - mn0);
            float p1 = ex2f(sacc[t][1] - mn0);
            float p2 = ex2f(sacc[t][2] - mn1);
            float p3 = ex2f(sacc[t][3] - mn1);
            sum0 += p0 + p1;
            sum1 += p2 + p3;
            __nv_bfloat16 h0 = __float2bfloat16(p0), h1 = __float2bfloat16(p1);
            __nv_bfloat16 h2 = __float2bfloat16(p2), h3 = __float2bfloat16(p3);
            int kk = t >> 1, o = (t & 1) * 2;
            {
                __nv_bfloat162 u; u.x = h0; u.y = h1;
                pa_hi[kk][o + 0] = *reinterpret_cast<uint32_t*>(&u);
            }
            {
                __nv_bfloat162 u; u.x = h2; u.y = h3;
                pa_hi[kk][o + 1] = *reinterpret_cast<uint32_t*>(&u);
            }
            pa_lo[kk][o + 0] = pack_bf2(p0 - __bfloat162float(h0),
                                        p1 - __bfloat162float(h1));
            pa_lo[kk][o + 1] = pack_bf2(p2 - __bfloat162float(h2),
                                        p3 - __bfloat162float(h3));
        }
        sum0 += __shfl_xor_sync(0xffffffffu, sum0, 1);
        sum0 += __shfl_xor_sync(0xffffffffu, sum0, 2);
        sum1 += __shfl_xor_sync(0xffffffffu, sum1, 1);
        sum1 += __shfl_xor_sync(0xffffffffu, sum1, 2);
        l0 = l0 * c0 + sum0;
        l1 = l1 * c1 + sum1;
#pragma unroll
        for (int t = 0; t < 8; t++) {
            oacc[t][0] *= c0; oacc[t][1] *= c0;
            oacc[t][2] *= c1; oacc[t][3] *= c1;
        }

#pragma unroll
        for (int kk = 0; kk < 4; kk++) {
            int colb = kk * 32 + ((lane >> 4) << 4);
#pragma unroll
            for (int dt = 0; dt < 4; dt++) {
                int row = dt * 16 + (lane & 15);
                uint32_t r0, r1, r2, r3;
                ldsm_x4(r0, r1, r2, r3, st + 16384 + sw128(row * 128 + colb));  // vhi
                mma_bf16(oacc[2 * dt + 0], pa_hi[kk][0], pa_hi[kk][1], pa_hi[kk][2],
                         pa_hi[kk][3], r0, r2);
                mma_bf16(oacc[2 * dt + 1], pa_hi[kk][0], pa_hi[kk][1], pa_hi[kk][2],
                         pa_hi[kk][3], r1, r3);
                mma_bf16(oacc[2 * dt + 0], pa_lo[kk][0], pa_lo[kk][1], pa_lo[kk][2],
                         pa_lo[kk][3], r0, r2);
                mma_bf16(oacc[2 * dt + 1], pa_lo[kk][0], pa_lo[kk][1], pa_lo[kk][2],
                         pa_lo[kk][3], r1, r3);
                uint32_t s0, s1, s2, s3;
                ldsm_x4(s0, s1, s2, s3, st + 24576 + sw128(row * 128 + colb));  // vlo
                mma_bf16(oacc[2 * dt + 0], pa_hi[kk][0], pa_hi[kk][1], pa_hi[kk][2],
                         pa_hi[kk][3], s0, s2);
                mma_bf16(oacc[2 * dt + 1], pa_hi[kk][0], pa_hi[kk][1], pa_hi[kk][2],
                         pa_hi[kk][3], s1, s3);
            }
        }

        __syncthreads();
        if (kb + 2 < NIT) load_kv(kb + 2, s);
    }

    float inv0 = 1.0f / l0, inv1 = 1.0f / l1;
    int r_g0 = qb * 128 + wid * 16 + (lane >> 2);
#pragma unroll
    for (int t = 0; t < 8; t++) {
        int col = h * 64 + t * 8 + (lane & 3) * 2;
        float2 v0 = make_float2(oacc[t][0] * inv0, oacc[t][1] * inv0);
        float2 v1 = make_float2(oacc[t][2] * inv1, oacc[t][3] * inv1);
        *(float2*)&Out[((size_t)b * SS + r_g0) * DD + col] = v0;
        *(float2*)&Out[((size_t)b * SS + r_g0 + 8) * DD + col] = v1;
    }
}

extern "C" void kernel_launch(void* const* d_in, const int* in_sizes, int n_in,
                              void* d_out, int out_size) {
    const float* X = (const float*)d_in[0];     // [16,1024,1024]
    const float* W = (const float*)d_in[1];     // [2048,1024]
    const float* bias = (const float*)d_in[2];  // [2048]
    float* Out = (float*)d_out;                 // [16,1024,1024]

    cudaFuncSetAttribute(gemm_hmma, cudaFuncAttributeMaxDynamicSharedMemorySize,
                         GEMM_SMEM);
    cudaFuncSetAttribute(attn_tc, cudaFuncAttributeMaxDynamicSharedMemorySize,
                         ATT_SMEM);

    conv_x<<<(BB * SS * DD + 255) / 256, 256>>>(X);
    conv_w<<<(2048 * 1024 + 255) / 256, 256>>>(W);
    conv_vt<<<dim3(16, HH, BB), 256>>>(X);
    gemm_hmma<<<dim3(32, 128), 256, GEMM_SMEM>>>(bias);

    attn_tc<<<dim3(SS / 128, HH, BB), 256, ATT_SMEM>>>(Out);
}

// round 10
// speedup vs baseline: 2.3434x; 1.5540x over previous
#include <cuda_runtime.h>
#include <cuda_bf16.h>
#include <cuda_fp16.h>
#include <cstdint>

// Problem constants
#define BB 16
#define SS 1024
#define DD 1024
#define HH 16
#define HD 64
#define K2 2048   // gemm split storage: [hi(1024) | lo(1024)]

// Scratch (static __device__ arrays -- no allocations)
__device__ __nv_bfloat16 g_xs[BB * SS * K2];        // 64 MB
__device__ __nv_bfloat16 g_ws[2048 * K2];           // 8 MB
// fp16 Q/K, head-major: [(b*16+h)*1024 + s][64]  (q pre-scaled by 0.125*log2e)
__device__ __half g_qh[BB * HH * SS * 64];          // 32 MB
__device__ __half g_kh[BB * HH * SS * 64];          // 32 MB
// V transposed fp16: [bh*64 + dim][1024 keys]
__device__ __half g_vt[BB * HH * 64 * SS];          // 32 MB

// ---------------------------------------------------------------------------
// PTX helpers (sm_80-level PTX; valid on compute_103)
// ---------------------------------------------------------------------------
__device__ __forceinline__ uint32_t smem_u32(const void* p) {
    uint32_t a;
    asm("{ .reg .u64 t; cvta.to.shared.u64 t, %1; cvt.u32.u64 %0, t; }"
        : "=r"(a) : "l"(p));
    return a;
}
__device__ __forceinline__ void cp16(uint32_t saddr, const void* g) {
    asm volatile("cp.async.cg.shared.global [%0], [%1], 16;" :: "r"(saddr), "l"(g));
}
__device__ __forceinline__ void ldsm_x4(uint32_t& r0, uint32_t& r1, uint32_t& r2,
                                        uint32_t& r3, uint32_t addr) {
    asm volatile("ldmatrix.sync.aligned.m8n8.x4.shared.b16 {%0,%1,%2,%3}, [%4];"
                 : "=r"(r0), "=r"(r1), "=r"(r2), "=r"(r3) : "r"(addr));
}
__device__ __forceinline__ void mma_bf16(float* c, uint32_t a0, uint32_t a1,
                                         uint32_t a2, uint32_t a3,
                                         uint32_t b0, uint32_t b1) {
    asm volatile(
        "mma.sync.aligned.m16n8k16.row.col.f32.bf16.bf16.f32 "
        "{%0,%1,%2,%3}, {%4,%5,%6,%7}, {%8,%9}, {%0,%1,%2,%3};"
        : "+f"(c[0]), "+f"(c[1]), "+f"(c[2]), "+f"(c[3])
        : "r"(a0), "r"(a1), "r"(a2), "r"(a3), "r"(b0), "r"(b1));
}
__device__ __forceinline__ void mma_f16(float* c, uint32_t a0, uint32_t a1,
                                        uint32_t a2, uint32_t a3,
                                        uint32_t b0, uint32_t b1) {
    asm volatile(
        "mma.sync.aligned.m16n8k16.row.col.f32.f16.f16.f32 "
        "{%0,%1,%2,%3}, {%4,%5,%6,%7}, {%8,%9}, {%0,%1,%2,%3};"
        : "+f"(c[0]), "+f"(c[1]), "+f"(c[2]), "+f"(c[3])
        : "r"(a0), "r"(a1), "r"(a2), "r"(a3), "r"(b0), "r"(b1));
}
__device__ __forceinline__ uint32_t sw128(uint32_t byte) {
    return byte ^ ((byte >> 3) & 0x70);
}
__device__ __forceinline__ float ex2f(float x) {
    float y;
    asm("ex2.approx.ftz.f32 %0, %1;" : "=f"(y) : "f"(x));
    return y;
}
__device__ __forceinline__ uint32_t pack_h2(float a, float b) {
    __half2 h = __floats2half2_rn(a, b);
    return *reinterpret_cast<uint32_t*>(&h);
}

// ---------------------------------------------------------------------------
// bf16 split conversion for the projection GEMM: row = [hi(1024) | lo(1024)]
// ---------------------------------------------------------------------------
__global__ void conv_x(const float* __restrict__ X) {
    int i = blockIdx.x * blockDim.x + threadIdx.x;
    if (i >= BB * SS * DD) return;
    int r = i >> 10, c = i & 1023;
    float x = X[i];
    __nv_bfloat16 hi = __float2bfloat16(x);
    __nv_bfloat16 lo = __float2bfloat16(x - __bfloat162float(hi));
    size_t base = (size_t)r * K2;
    g_xs[base + c] = hi;
    g_xs[base + 1024 + c] = lo;
}
__global__ void conv_w(const float* __restrict__ W) {
    int i = blockIdx.x * blockDim.x + threadIdx.x;
    if (i >= 2048 * 1024) return;
    int r = i >> 10, c = i & 1023;
    float w = W[i];
    __nv_bfloat16 hi = __float2bfloat16(w);
    __nv_bfloat16 lo = __float2bfloat16(w - __bfloat162float(hi));
    size_t base = (size_t)r * K2;
    g_ws[base + c] = hi;
    g_ws[base + 1024 + c] = lo;
}

// V transpose to fp16: per (kb, h, b) tile of 64 keys x 64 dims
__global__ __launch_bounds__(256) void conv_vt(const float* __restrict__ X) {
    __shared__ float tile[64][65];
    int kb = blockIdx.x, h = blockIdx.y, b = blockIdx.z;
    int tid = threadIdx.x;
#pragma unroll
    for (int i = 0; i < 4; i++) {
        int row = i * 16 + tid / 16;
        int c4 = (tid % 16) * 4;
        float4 v = *(const float4*)&X[((size_t)b * SS + kb * 64 + row) * DD + h * 64 + c4];
        tile[row][c4 + 0] = v.x;
        tile[row][c4 + 1] = v.y;
        tile[row][c4 + 2] = v.z;
        tile[row][c4 + 3] = v.w;
    }
    __syncthreads();
    int bh = b * HH + h;
#pragma unroll
    for (int i = 0; i < 16; i++) {
        int e = tid + i * 256;
        int dim = e >> 6, key = e & 63;
        g_vt[((size_t)bh * 64 + dim) * SS + kb * 64 + key] = __float2half(tile[key][dim]);
    }
}

// ---------------------------------------------------------------------------
// HMMA bf16 GEMM, 3-term split with hi-fragment reuse (R9 config).
// Epilogue now emits fp16 q/k directly (q pre-scaled by 0.125*log2e).
// ---------------------------------------------------------------------------
#define BKH 32
#define NSTAGE 3
#define STAGE_BYTES 24576              // A 16KB + B 8KB
#define GEMM_SMEM (NSTAGE * STAGE_BYTES)

__global__ __launch_bounds__(256, 3) void gemm_hmma(const float* __restrict__ bias) {
    extern __shared__ char smem[];
    const uint32_t sbase = smem_u32(smem);
    const int tid = threadIdx.x;
    const int lane = tid & 31;
    const int wid = tid >> 5;
    const int warp_m = wid & 3;
    const int warp_n = wid >> 2;
    const int n0 = blockIdx.x * 64;
    const int m0 = blockIdx.y * 128;

    const __nv_bfloat16* gA = g_xs + (size_t)m0 * K2;
    const __nv_bfloat16* gB = g_ws + (size_t)n0 * K2;

    auto load_stage = [&](int kc, int s) {
        uint32_t sA = sbase + s * STAGE_BYTES;
        uint32_t sB = sA + 16384;
        const __nv_bfloat16* a = gA + kc * BKH;
        const __nv_bfloat16* b = gB + kc * BKH;
#pragma unroll
        for (int i = 0; i < 4; i++) {
            int idx = tid + i * 256;
            int r = idx >> 3, q = idx & 7;
            uint32_t sw = sw128(r * 128 + q * 16);
            size_t goff = (size_t)r * K2 + (q >> 2) * 1024 + (q & 3) * 8;
            cp16(sA + sw, a + goff);
        }
#pragma unroll
        for (int i = 0; i < 2; i++) {
            int idx = tid + i * 256;
            int r = idx >> 3, q = idx & 7;
            uint32_t sw = sw128(r * 128 + q * 16);
            size_t goff = (size_t)r * K2 + (q >> 2) * 1024 + (q & 3) * 8;
            cp16(sB + sw, b + goff);
        }
        asm volatile("cp.async.commit_group;" ::: "memory");
    };

    float acc[2][4][4];
#pragma unroll
    for (int mi = 0; mi < 2; mi++)
#pragma unroll
        for (int nt = 0; nt < 4; nt++)
#pragma unroll
            for (int k = 0; k < 4; k++) acc[mi][nt][k] = 0.0f;

    const int NK = 1024 / BKH;  // 32
    load_stage(0, 0);
    load_stage(1, 1);

    for (int kc = 0; kc < NK; kc++) {
        int s = kc % NSTAGE;
        if (kc + 1 < NK) asm volatile("cp.async.wait_group 1;" ::: "memory");
        else             asm volatile("cp.async.wait_group 0;" ::: "memory");
        __syncthreads();
        if (kc + 2 < NK) load_stage(kc + 2, (kc + 2) % NSTAGE);

        uint32_t sA = sbase + s * STAGE_BYTES;
        uint32_t sB = sA + 16384;

#pragma unroll
        for (int kk = 0; kk < 2; kk++) {
            int colh = kk * 32 + ((lane >> 4) << 4);
            int coll = 64 + colh;
            uint32_t ah[2][4];
#pragma unroll
            for (int mi = 0; mi < 2; mi++) {
                int row = warp_m * 32 + mi * 16 + (lane & 15);
                ldsm_x4(ah[mi][0], ah[mi][1], ah[mi][2], ah[mi][3],
                        sA + sw128(row * 128 + colh));
            }
            uint32_t bh[2][4], bl[2][4];
#pragma unroll
            for (int p = 0; p < 2; p++) {
                int row = warp_n * 32 + p * 16 + (lane & 15);
                ldsm_x4(bh[p][0], bh[p][1], bh[p][2], bh[p][3],
                        sB + sw128(row * 128 + colh));
                ldsm_x4(bl[p][0], bl[p][1], bl[p][2], bl[p][3],
                        sB + sw128(row * 128 + coll));
            }
#pragma unroll
            for (int mi = 0; mi < 2; mi++) {
#pragma unroll
                for (int p = 0; p < 2; p++) {
                    mma_bf16(acc[mi][p * 2 + 0], ah[mi][0], ah[mi][1], ah[mi][2],
                             ah[mi][3], bh[p][0], bh[p][2]);
                    mma_bf16(acc[mi][p * 2 + 1], ah[mi][0], ah[mi][1], ah[mi][2],
                             ah[mi][3], bh[p][1], bh[p][3]);
                    mma_bf16(acc[mi][p * 2 + 0], ah[mi][0], ah[mi][1], ah[mi][2],
                             ah[mi][3], bl[p][0], bl[p][2]);
                    mma_bf16(acc[mi][p * 2 + 1], ah[mi][0], ah[mi][1], ah[mi][2],
                             ah[mi][3], bl[p][1], bl[p][3]);
                }
            }
#pragma unroll
            for (int mi = 0; mi < 2; mi++) {
                uint32_t al0, al1, al2, al3;
                int row = warp_m * 32 + mi * 16 + (lane & 15);
                ldsm_x4(al0, al1, al2, al3, sA + sw128(row * 128 + coll));
#pragma unroll
                for (int p = 0; p < 2; p++) {
                    mma_bf16(acc[mi][p * 2 + 0], al0, al1, al2, al3,
                             bh[p][0], bh[p][2]);
                    mma_bf16(acc[mi][p * 2 + 1], al0, al1, al2, al3,
                             bh[p][1], bh[p][3]);
                }
            }
        }
    }
    __syncthreads();

    // Epilogue: bias, scale (q only), fp16 store head-major
    const float QSCALE = 0.18033688011112042f;  // 0.125 * log2(e)
    float scale = (n0 < 1024) ? QSCALE : 1.0f;
    __half* dst = (n0 < 1024) ? g_qh : g_kh;

#pragma unroll
    for (int mi = 0; mi < 2; mi++) {
#pragma unroll
        for (int nt = 0; nt < 4; nt++) {
            int c = warp_n * 32 + nt * 8 + (lane & 3) * 2;
            int nn = (n0 + c) & 1023;
            int hh_ = nn >> 6, d = nn & 63;
            float b0 = __ldg(&bias[n0 + c]);
            float b1 = __ldg(&bias[n0 + c + 1]);
#pragma unroll
            for (int rr = 0; rr < 2; rr++) {
                int r = m0 + warp_m * 32 + mi * 16 + (lane >> 2) + rr * 8;
                int bb = r >> 10, s2 = r & 1023;
                size_t base = ((size_t)(bb * HH + hh_) * SS + s2) * 64;
                float v0 = (acc[mi][nt][rr * 2 + 0] + b0) * scale;
                float v1 = (acc[mi][nt][rr * 2 + 1] + b1) * scale;
                *(__half2*)&dst[base + d] = __floats2half2_rn(v0, v1);
            }
        }
    }
}

// ---------------------------------------------------------------------------
// fp16 single-pass flash attention. CTA = (128 q-rows, h, b), 8 warps x 16
// rows, BN=64 keys/iter, 2-stage cp.async. QK and PV are ONE fp16 pass each.
// ---------------------------------------------------------------------------
#define ATT_SMEM (16384 + 2 * 16384)  // Q 16KB + 2 stages x (K 8KB + V 8KB)

__global__ __launch_bounds__(256) void attn_tc(float* __restrict__ Out) {
    extern __shared__ char smem[];
    const uint32_t sb = smem_u32(smem);
    const int tid = threadIdx.x;
    const int lane = tid & 31;
    const int wid = tid >> 5;
    const int qb = blockIdx.x, h = blockIdx.y, b = blockIdx.z;
    const int bh = b * HH + h;

    const uint32_t QT = sb;                         // 128 rows x 128B
    auto STAGE = [&](int s) { return sb + 16384 + s * 16384; };  // K | V

    // Load Q tile (128 rows x 64 fp16)
    {
        const __half* qsrc = g_qh + ((size_t)bh * SS + qb * 128) * 64;
#pragma unroll
        for (int i = 0; i < 4; i++) {
            int e = tid + i * 256;
            int row = e >> 3, q = e & 7;
            uint32_t sw = sw128(row * 128 + q * 16);
            cp16(QT + sw, qsrc + (size_t)row * 64 + q * 8);
        }
        asm volatile("cp.async.commit_group;" ::: "memory");
    }

    auto load_kv = [&](int kb, int s) {
        uint32_t st = STAGE(s);
        const __half* ks = g_kh + ((size_t)bh * SS + kb * 64) * 64;
        const __half* vt = g_vt + (size_t)bh * 64 * SS + kb * 64;
#pragma unroll
        for (int i = 0; i < 2; i++) {
            int e = tid + i * 256;
            int row = e >> 3, q = e & 7;
            uint32_t sw = sw128(row * 128 + q * 16);
            cp16(st + sw, ks + (size_t)row * 64 + q * 8);
            cp16(st + 8192 + sw, vt + (size_t)row * SS + q * 8);
        }
        asm volatile("cp.async.commit_group;" ::: "memory");
    };

    load_kv(0, 0);
    load_kv(1, 1);

    // Preload Q fragments (loop-invariant; 16 regs)
    asm volatile("cp.async.wait_group 2;" ::: "memory");
    __syncthreads();
    uint32_t qf[4][4];
    {
        int row = wid * 16 + (lane & 15);
#pragma unroll
        for (int kk = 0; kk < 4; kk++) {
            int colb = kk * 32 + ((lane >> 4) << 4);
            ldsm_x4(qf[kk][0], qf[kk][1], qf[kk][2], qf[kk][3],
                    QT + sw128(row * 128 + colb));
        }
    }

    float oacc[8][4];
#pragma unroll
    for (int t = 0; t < 8; t++)
#pragma unroll
        for (int k = 0; k < 4; k++) oacc[t][k] = 0.0f;
    float m0 = -1e30f, m1 = -1e30f, l0 = 0.0f, l1 = 0.0f;

    const int NIT = SS / 64;  // 16
    for (int kb = 0; kb < NIT; kb++) {
        int s = kb & 1;
        if (kb + 1 < NIT) asm volatile("cp.async.wait_group 1;" ::: "memory");
        else              asm volatile("cp.async.wait_group 0;" ::: "memory");
        __syncthreads();

        uint32_t st = STAGE(s);

        // ---- S = Q K^T, single fp16 pass ----
        float sacc[8][4];
#pragma unroll
        for (int t = 0; t < 8; t++)
#pragma unroll
            for (int k = 0; k < 4; k++) sacc[t][k] = 0.0f;

#pragma unroll
        for (int kk = 0; kk < 4; kk++) {
            int colb = kk * 32 + ((lane >> 4) << 4);
#pragma unroll
            for (int p = 0; p < 4; p++) {
                int row = p * 16 + (lane & 15);
                uint32_t r0, r1, r2, r3;
                ldsm_x4(r0, r1, r2, r3, st + sw128(row * 128 + colb));
                mma_f16(sacc[2 * p + 0], qf[kk][0], qf[kk][1], qf[kk][2], qf[kk][3], r0, r2);
                mma_f16(sacc[2 * p + 1], qf[kk][0], qf[kk][1], qf[kk][2], qf[kk][3], r1, r3);
            }
        }

        // ---- online softmax (scores in log2 domain) ----
        float mx0 = -1e30f, mx1 = -1e30f;
#pragma unroll
        for (int t = 0; t < 8; t++) {
            mx0 = fmaxf(mx0, fmaxf(sacc[t][0], sacc[t][1]));
            mx1 = fmaxf(mx1, fmaxf(sacc[t][2], sacc[t][3]));
        }
        mx0 = fmaxf(mx0, __shfl_xor_sync(0xffffffffu, mx0, 1));
        mx0 = fmaxf(mx0, __shfl_xor_sync(0xffffffffu, mx0, 2));
        mx1 = fmaxf(mx1, __shfl_xor_sync(0xffffffffu, mx1, 1));
        mx1 = fmaxf(mx1, __shfl_xor_sync(0xffffffffu, mx1, 2));
        float mn0 = fmaxf(m0, mx0), mn1 = fmaxf(m1, mx1);
        float c0 = ex2f(m0 - mn0), c1 = ex2f(m1 - mn1);
        m0 = mn0; m1 = mn1;

        uint32_t pa[4][4];
        float sum0 = 0.0f, sum1 = 0.0f;
#pragma unroll
        for (int t = 0; t < 8; t++) {
            float p0 = ex2f(sacc[t][0] - mn0);
            float p1 = ex2f(sacc[t][1] - mn0);
            float p2 = ex2f(sacc[t][2] - mn1);
            float p3 = ex2f(sacc[t][3] - mn1);
            sum0 += p0 + p1;
            sum1 += p2 + p3;
            int kk = t >> 1, o = (t & 1) * 2;
            pa[kk][o + 0] = pack_h2(p0, p1);
            pa[kk][o + 1] = pack_h2(p2, p3);
        }
        sum0 += __shfl_xor_sync(0xffffffffu, sum0, 1);
        sum0 += __shfl_xor_sync(0xffffffffu, sum0, 2);
        sum1 += __shfl_xor_sync(0xffffffffu, sum1, 1);
        sum1 += __shfl_xor_sync(0xffffffffu, sum1, 2);
        l0 = l0 * c0 + sum0;
        l1 = l1 * c1 + sum1;
#pragma unroll
        for (int t = 0; t < 8; t++) {
            oacc[t][0] *= c0; oacc[t][1] *= c0;
            oacc[t][2] *= c1; oacc[t][3] *= c1;
        }

        // ---- O += P V, single fp16 pass ----
#pragma unroll
        for (int kk = 0; kk < 4; kk++) {
            int colb = kk * 32 + ((lane >> 4) << 4);
#pragma unroll
            for (int dt = 0; dt < 4; dt++) {
                int row = dt * 16 + (lane & 15);
                uint32_t r0, r1, r2, r3;
                ldsm_x4(r0, r1, r2, r3, st + 8192 + sw128(row * 128 + colb));
                mma_f16(oacc[2 * dt + 0], pa[kk][0], pa[kk][1], pa[kk][2],
                        pa[kk][3], r0, r2);
                mma_f16(oacc[2 * dt + 1], pa[kk][0], pa[kk][1], pa[kk][2],
                        pa[kk][3], r1, r3);
            }
        }

        __syncthreads();
        if (kb + 2 < NIT) load_kv(kb + 2, s);
    }

    // ---- epilogue ----
    float inv0 = 1.0f / l0, inv1 = 1.0f / l1;
    int r_g0 = qb * 128 + wid * 16 + (lane >> 2);
#pragma unroll
    for (int t = 0; t < 8; t++) {
        int col = h * 64 + t * 8 + (lane & 3) * 2;
        float2 v0 = make_float2(oacc[t][0] * inv0, oacc[t][1] * inv0);
        float2 v1 = make_float2(oacc[t][2] * inv1, oacc[t][3] * inv1);
        *(float2*)&Out[((size_t)b * SS + r_g0) * DD + col] = v0;
        *(float2*)&Out[((size_t)b * SS + r_g0 + 8) * DD + col] = v1;
    }
}

extern "C" void kernel_launch(void* const* d_in, const int* in_sizes, int n_in,
                              void* d_out, int out_size) {
    const float* X = (const float*)d_in[0];     // [16,1024,1024]
    const float* W = (const float*)d_in[1];     // [2048,1024]
    const float* bias = (const float*)d_in[2];  // [2048]
    float* Out = (float*)d_out;                 // [16,1024,1024]

    cudaFuncSetAttribute(gemm_hmma, cudaFuncAttributeMaxDynamicSharedMemorySize,
                         GEMM_SMEM);
    cudaFuncSetAttribute(attn_tc, cudaFuncAttributeMaxDynamicSharedMemorySize,
                         ATT_SMEM);

    conv_x<<<(BB * SS * DD + 255) / 256, 256>>>(X);
    conv_w<<<(2048 * 1024 + 255) / 256, 256>>>(W);
    conv_vt<<<dim3(16, HH, BB), 256>>>(X);
    gemm_hmma<<<dim3(32, 128), 256, GEMM_SMEM>>>(bias);

    attn_tc<<<dim3(SS / 128, HH, BB), 256, ATT_SMEM>>>(Out);
}

// round 11
// speedup vs baseline: 4.4629x; 1.9045x over previous
#include <cuda_runtime.h>
#include <cuda_bf16.h>
#include <cuda_fp16.h>
#include <cstdint>

// Problem constants
#define BB 16
#define SS 1024
#define DD 1024
#define HH 16
#define HD 64

// Scratch (static __device__ arrays -- no allocations)
__device__ __half g_xh[BB * SS * DD];               // 32 MB  fp16 X
__device__ __half g_wh[2048 * DD];                  // 4 MB   fp16 W
// fp16 Q/K, head-major: [(b*16+h)*1024 + s][64]  (q pre-scaled by 0.125*log2e)
__device__ __half g_qh[BB * HH * SS * 64];          // 32 MB
__device__ __half g_kh[BB * HH * SS * 64];          // 32 MB
// V transposed fp16: [bh*64 + dim][1024 keys]
__device__ __half g_vt[BB * HH * 64 * SS];          // 32 MB

// ---------------------------------------------------------------------------
// PTX helpers (sm_80-level PTX; valid on compute_103)
// ---------------------------------------------------------------------------
__device__ __forceinline__ uint32_t smem_u32(const void* p) {
    uint32_t a;
    asm("{ .reg .u64 t; cvta.to.shared.u64 t, %1; cvt.u32.u64 %0, t; }"
        : "=r"(a) : "l"(p));
    return a;
}
__device__ __forceinline__ void cp16(uint32_t saddr, const void* g) {
    asm volatile("cp.async.cg.shared.global [%0], [%1], 16;" :: "r"(saddr), "l"(g));
}
__device__ __forceinline__ void ldsm_x4(uint32_t& r0, uint32_t& r1, uint32_t& r2,
                                        uint32_t& r3, uint32_t addr) {
    asm volatile("ldmatrix.sync.aligned.m8n8.x4.shared.b16 {%0,%1,%2,%3}, [%4];"
                 : "=r"(r0), "=r"(r1), "=r"(r2), "=r"(r3) : "r"(addr));
}
__device__ __forceinline__ void mma_f16(float* c, uint32_t a0, uint32_t a1,
                                        uint32_t a2, uint32_t a3,
                                        uint32_t b0, uint32_t b1) {
    asm volatile(
        "mma.sync.aligned.m16n8k16.row.col.f32.f16.f16.f32 "
        "{%0,%1,%2,%3}, {%4,%5,%6,%7}, {%8,%9}, {%0,%1,%2,%3};"
        : "+f"(c[0]), "+f"(c[1]), "+f"(c[2]), "+f"(c[3])
        : "r"(a0), "r"(a1), "r"(a2), "r"(a3), "r"(b0), "r"(b1));
}
__device__ __forceinline__ uint32_t sw128(uint32_t byte) {
    return byte ^ ((byte >> 3) & 0x70);
}
__device__ __forceinline__ float ex2f(float x) {
    float y;
    asm("ex2.approx.ftz.f32 %0, %1;" : "=f"(y) : "f"(x));
    return y;
}
__device__ __forceinline__ uint32_t pack_h2(float a, float b) {
    __half2 h = __floats2half2_rn(a, b);
    return *reinterpret_cast<uint32_t*>(&h);
}

// ---------------------------------------------------------------------------
// fp16 conversion kernels
// ---------------------------------------------------------------------------
__global__ void conv_x(const float* __restrict__ X) {
    int i = blockIdx.x * blockDim.x + threadIdx.x;
    int e = i * 4;
    if (e >= BB * SS * DD) return;
    float4 v = *(const float4*)&X[e];
    __half2 h0 = __floats2half2_rn(v.x, v.y);
    __half2 h1 = __floats2half2_rn(v.z, v.w);
    *(__half2*)&g_xh[e] = h0;
    *(__half2*)&g_xh[e + 2] = h1;
}
__global__ void conv_w(const float* __restrict__ W) {
    int i = blockIdx.x * blockDim.x + threadIdx.x;
    int e = i * 4;
    if (e >= 2048 * DD) return;
    float4 v = *(const float4*)&W[e];
    __half2 h0 = __floats2half2_rn(v.x, v.y);
    __half2 h1 = __floats2half2_rn(v.z, v.w);
    *(__half2*)&g_wh[e] = h0;
    *(__half2*)&g_wh[e + 2] = h1;
}

// V transpose to fp16: per (kb, h, b) tile of 64 keys x 64 dims
__global__ __launch_bounds__(256) void conv_vt(const float* __restrict__ X) {
    __shared__ float tile[64][65];
    int kb = blockIdx.x, h = blockIdx.y, b = blockIdx.z;
    int tid = threadIdx.x;
#pragma unroll
    for (int i = 0; i < 4; i++) {
        int row = i * 16 + tid / 16;
        int c4 = (tid % 16) * 4;
        float4 v = *(const float4*)&X[((size_t)b * SS + kb * 64 + row) * DD + h * 64 + c4];
        tile[row][c4 + 0] = v.x;
        tile[row][c4 + 1] = v.y;
        tile[row][c4 + 2] = v.z;
        tile[row][c4 + 3] = v.w;
    }
    __syncthreads();
    int bh = b * HH + h;
#pragma unroll
    for (int i = 0; i < 16; i++) {
        int e = tid + i * 256;
        int dim = e >> 6, key = e & 63;
        g_vt[((size_t)bh * 64 + dim) * SS + kb * 64 + key] = __float2half(tile[key][dim]);
    }
}

// ---------------------------------------------------------------------------
// fp16 single-pass HMMA GEMM: C[16384,2048] = Xh @ Wh^T + bias (K=1024).
// CTA 128x128, BK=64, 3-stage cp.async, 8 warps (2x4), warp tile 64x32.
// Epilogue emits fp16 q/k head-major (q pre-scaled by 0.125*log2e).
// ---------------------------------------------------------------------------
#define BK 64
#define NSTAGE 3
#define STAGE_BYTES 32768              // A 16KB + B 16KB
#define GEMM_SMEM (NSTAGE * STAGE_BYTES)

__global__ __launch_bounds__(256) void gemm_hmma(const float* __restrict__ bias) {
    extern __shared__ char smem[];
    const uint32_t sbase = smem_u32(smem);
    const int tid = threadIdx.x;
    const int lane = tid & 31;
    const int wid = tid >> 5;
    const int warp_m = wid >> 2;        // 0..1
    const int warp_n = wid & 3;         // 0..3
    const int n0 = blockIdx.x * 128;
    const int m0 = blockIdx.y * 128;

    const __half* gA = g_xh + (size_t)m0 * DD;
    const __half* gB = g_wh + (size_t)n0 * DD;

    auto load_stage = [&](int kc, int s) {
        uint32_t sA = sbase + s * STAGE_BYTES;
        uint32_t sB = sA + 16384;
        const __half* a = gA + kc * BK;
        const __half* b = gB + kc * BK;
#pragma unroll
        for (int i = 0; i < 4; i++) {
            int idx = tid + i * 256;            // 0..1023
            int r = idx >> 3, q = idx & 7;
            uint32_t sw = sw128(r * 128 + q * 16);
            cp16(sA + sw, a + (size_t)r * DD + q * 8);
            cp16(sB + sw, b + (size_t)r * DD + q * 8);
        }
        asm volatile("cp.async.commit_group;" ::: "memory");
    };

    float acc[4][4][4];
#pragma unroll
    for (int mi = 0; mi < 4; mi++)
#pragma unroll
        for (int nt = 0; nt < 4; nt++)
#pragma unroll
            for (int k = 0; k < 4; k++) acc[mi][nt][k] = 0.0f;

    const int NK = DD / BK;  // 16
    load_stage(0, 0);
    load_stage(1, 1);

    for (int kc = 0; kc < NK; kc++) {
        int s = kc % NSTAGE;
        if (kc + 1 < NK) asm volatile("cp.async.wait_group 1;" ::: "memory");
        else             asm volatile("cp.async.wait_group 0;" ::: "memory");
        __syncthreads();
        if (kc + 2 < NK) load_stage(kc + 2, (kc + 2) % NSTAGE);

        uint32_t sA = sbase + s * STAGE_BYTES;
        uint32_t sB = sA + 16384;

#pragma unroll
        for (int kk = 0; kk < BK / 16; kk++) {   // 4 k16 steps
            uint32_t a[4][4], bfr[2][4];
            int colb = kk * 32 + ((lane >> 4) << 4);
#pragma unroll
            for (int mi = 0; mi < 4; mi++) {
                int row = warp_m * 64 + mi * 16 + (lane & 15);
                ldsm_x4(a[mi][0], a[mi][1], a[mi][2], a[mi][3],
                        sA + sw128(row * 128 + colb));
            }
#pragma unroll
            for (int p = 0; p < 2; p++) {
                int row = warp_n * 32 + p * 16 + (lane & 15);
                ldsm_x4(bfr[p][0], bfr[p][1], bfr[p][2], bfr[p][3],
                        sB + sw128(row * 128 + colb));
            }
#pragma unroll
            for (int mi = 0; mi < 4; mi++) {
#pragma unroll
                for (int p = 0; p < 2; p++) {
                    mma_f16(acc[mi][p * 2 + 0], a[mi][0], a[mi][1], a[mi][2], a[mi][3],
                            bfr[p][0], bfr[p][2]);
                    mma_f16(acc[mi][p * 2 + 1], a[mi][0], a[mi][1], a[mi][2], a[mi][3],
                            bfr[p][1], bfr[p][3]);
                }
            }
        }
    }
    __syncthreads();

    // Epilogue: bias, scale (q only), fp16 store head-major
    const float QSCALE = 0.18033688011112042f;  // 0.125 * log2(e)
    float scale = (n0 < 1024) ? QSCALE : 1.0f;
    __half* dst = (n0 < 1024) ? g_qh : g_kh;

#pragma unroll
    for (int mi = 0; mi < 4; mi++) {
#pragma unroll
        for (int nt = 0; nt < 4; nt++) {
            int c = warp_n * 32 + nt * 8 + (lane & 3) * 2;
            int nn = (n0 + c) & 1023;
            int hh_ = nn >> 6, d = nn & 63;
            float b0 = __ldg(&bias[n0 + c]);
            float b1 = __ldg(&bias[n0 + c + 1]);
#pragma unroll
            for (int rr = 0; rr < 2; rr++) {
                int r = m0 + warp_m * 64 + mi * 16 + (lane >> 2) + rr * 8;
                int bb = r >> 10, s2 = r & 1023;
                size_t base = ((size_t)(bb * HH + hh_) * SS + s2) * 64;
                float v0 = (acc[mi][nt][rr * 2 + 0] + b0) * scale;
                float v1 = (acc[mi][nt][rr * 2 + 1] + b1) * scale;
                *(__half2*)&dst[base + d] = __floats2half2_rn(v0, v1);
            }
        }
    }
}

// ---------------------------------------------------------------------------
// fp16 single-pass flash attention (unchanged from R10).
// ---------------------------------------------------------------------------
#define ATT_SMEM (16384 + 2 * 16384)  // Q 16KB + 2 stages x (K 8KB + V 8KB)

__global__ __launch_bounds__(256) void attn_tc(float* __restrict__ Out) {
    extern __shared__ char smem[];
    const uint32_t sb = smem_u32(smem);
    const int tid = threadIdx.x;
    const int lane = tid & 31;
    const int wid = tid >> 5;
    const int qb = blockIdx.x, h = blockIdx.y, b = blockIdx.z;
    const int bh = b * HH + h;

    const uint32_t QT = sb;
    auto STAGE = [&](int s) { return sb + 16384 + s * 16384; };

    {
        const __half* qsrc = g_qh + ((size_t)bh * SS + qb * 128) * 64;
#pragma unroll
        for (int i = 0; i < 4; i++) {
            int e = tid + i * 256;
            int row = e >> 3, q = e & 7;
            uint32_t sw = sw128(row * 128 + q * 16);
            cp16(QT + sw, qsrc + (size_t)row * 64 + q * 8);
        }
        asm volatile("cp.async.commit_group;" ::: "memory");
    }

    auto load_kv = [&](int kb, int s) {
        uint32_t st = STAGE(s);
        const __half* ks = g_kh + ((size_t)bh * SS + kb * 64) * 64;
        const __half* vt = g_vt + (size_t)bh * 64 * SS + kb * 64;
#pragma unroll
        for (int i = 0; i < 2; i++) {
            int e = tid + i * 256;
            int row = e >> 3, q = e & 7;
            uint32_t sw = sw128(row * 128 + q * 16);
            cp16(st + sw, ks + (size_t)row * 64 + q * 8);
            cp16(st + 8192 + sw, vt + (size_t)row * SS + q * 8);
        }
        asm volatile("cp.async.commit_group;" ::: "memory");
    };

    load_kv(0, 0);
    load_kv(1, 1);

    asm volatile("cp.async.wait_group 2;" ::: "memory");
    __syncthreads();
    uint32_t qf[4][4];
    {
        int row = wid * 16 + (lane & 15);
#pragma unroll
        for (int kk = 0; kk < 4; kk++) {
            int colb = kk * 32 + ((lane >> 4) << 4);
            ldsm_x4(qf[kk][0], qf[kk][1], qf[kk][2], qf[kk][3],
                    QT + sw128(row * 128 + colb));
        }
    }

    float oacc[8][4];
#pragma unroll
    for (int t = 0; t < 8; t++)
#pragma unroll
        for (int k = 0; k < 4; k++) oacc[t][k] = 0.0f;
    float m0 = -1e30f, m1 = -1e30f, l0 = 0.0f, l1 = 0.0f;

    const int NIT = SS / 64;  // 16
    for (int kb = 0; kb < NIT; kb++) {
        int s = kb & 1;
        if (kb + 1 < NIT) asm volatile("cp.async.wait_group 1;" ::: "memory");
        else              asm volatile("cp.async.wait_group 0;" ::: "memory");
        __syncthreads();

        uint32_t st = STAGE(s);

        float sacc[8][4];
#pragma unroll
        for (int t = 0; t < 8; t++)
#pragma unroll
            for (int k = 0; k < 4; k++) sacc[t][k] = 0.0f;

#pragma unroll
        for (int kk = 0; kk < 4; kk++) {
            int colb = kk * 32 + ((lane >> 4) << 4);
#pragma unroll
            for (int p = 0; p < 4; p++) {
                int row = p * 16 + (lane & 15);
                uint32_t r0, r1, r2, r3;
                ldsm_x4(r0, r1, r2, r3, st + sw128(row * 128 + colb));
                mma_f16(sacc[2 * p + 0], qf[kk][0], qf[kk][1], qf[kk][2], qf[kk][3], r0, r2);
                mma_f16(sacc[2 * p + 1], qf[kk][0], qf[kk][1], qf[kk][2], qf[kk][3], r1, r3);
            }
        }

        float mx0 = -1e30f, mx1 = -1e30f;
#pragma unroll
        for (int t = 0; t < 8; t++) {
            mx0 = fmaxf(mx0, fmaxf(sacc[t][0], sacc[t][1]));
            mx1 = fmaxf(mx1, fmaxf(sacc[t][2], sacc[t][3]));
        }
        mx0 = fmaxf(mx0, __shfl_xor_sync(0xffffffffu, mx0, 1));
        mx0 = fmaxf(mx0, __shfl_xor_sync(0xffffffffu, mx0, 2));
        mx1 = fmaxf(mx1, __shfl_xor_sync(0xffffffffu, mx1, 1));
        mx1 = fmaxf(mx1, __shfl_xor_sync(0xffffffffu, mx1, 2));
        float mn0 = fmaxf(m0, mx0), mn1 = fmaxf(m1, mx1);
        float c0 = ex2f(m0 - mn0), c1 = ex2f(m1 - mn1);
        m0 = mn0; m1 = mn1;

        uint32_t pa[4][4];
        float sum0 = 0.0f, sum1 = 0.0f;
#pragma unroll
        for (int t = 0; t < 8; t++) {
            float p0 = ex2f(sacc[t][0] - mn0);
            float p1 = ex2f(sacc[t][1] - mn0);
            float p2 = ex2f(sacc[t][2] - mn1);
            float p3 = ex2f(sacc[t][3] - mn1);
            sum0 += p0 + p1;
            sum1 += p2 + p3;
            int kk = t >> 1, o = (t & 1) * 2;
            pa[kk][o + 0] = pack_h2(p0, p1);
            pa[kk][o + 1] = pack_h2(p2, p3);
        }
        sum0 += __shfl_xor_sync(0xffffffffu, sum0, 1);
        sum0 += __shfl_xor_sync(0xffffffffu, sum0, 2);
        sum1 += __shfl_xor_sync(0xffffffffu, sum1, 1);
        sum1 += __shfl_xor_sync(0xffffffffu, sum1, 2);
        l0 = l0 * c0 + sum0;
        l1 = l1 * c1 + sum1;
#pragma unroll
        for (int t = 0; t < 8; t++) {
            oacc[t][0] *= c0; oacc[t][1] *= c0;
            oacc[t][2] *= c1; oacc[t][3] *= c1;
        }

#pragma unroll
        for (int kk = 0; kk < 4; kk++) {
            int colb = kk * 32 + ((lane >> 4) << 4);
#pragma unroll
            for (int dt = 0; dt < 4; dt++) {
                int row = dt * 16 + (lane & 15);
                uint32_t r0, r1, r2, r3;
                ldsm_x4(r0, r1, r2, r3, st + 8192 + sw128(row * 128 + colb));
                mma_f16(oacc[2 * dt + 0], pa[kk][0], pa[kk][1], pa[kk][2],
                        pa[kk][3], r0, r2);
                mma_f16(oacc[2 * dt + 1], pa[kk][0], pa[kk][1], pa[kk][2],
                        pa[kk][3], r1, r3);
            }
        }

        __syncthreads();
        if (kb + 2 < NIT) load_kv(kb + 2, s);
    }

    float inv0 = 1.0f / l0, inv1 = 1.0f / l1;
    int r_g0 = qb * 128 + wid * 16 + (lane >> 2);
#pragma unroll
    for (int t = 0; t < 8; t++) {
        int col = h * 64 + t * 8 + (lane & 3) * 2;
        float2 v0 = make_float2(oacc[t][0] * inv0, oacc[t][1] * inv0);
        float2 v1 = make_float2(oacc[t][2] * inv1, oacc[t][3] * inv1);
        *(float2*)&Out[((size_t)b * SS + r_g0) * DD + col] = v0;
        *(float2*)&Out[((size_t)b * SS + r_g0 + 8) * DD + col] = v1;
    }
}

extern "C" void kernel_launch(void* const* d_in, const int* in_sizes, int n_in,
                              void* d_out, int out_size) {
    const float* X = (const float*)d_in[0];     // [16,1024,1024]
    const float* W = (const float*)d_in[1];     // [2048,1024]
    const float* bias = (const float*)d_in[2];  // [2048]
    float* Out = (float*)d_out;                 // [16,1024,1024]

    cudaFuncSetAttribute(gemm_hmma, cudaFuncAttributeMaxDynamicSharedMemorySize,
                         GEMM_SMEM);
    cudaFuncSetAttribute(attn_tc, cudaFuncAttributeMaxDynamicSharedMemorySize,
                         ATT_SMEM);

    conv_x<<<(BB * SS * DD / 4 + 255) / 256, 256>>>(X);
    conv_w<<<(2048 * DD / 4 + 255) / 256, 256>>>(W);
    conv_vt<<<dim3(16, HH, BB), 256>>>(X);
    gemm_hmma<<<dim3(16, 128), 256, GEMM_SMEM>>>(bias);

    attn_tc<<<dim3(SS / 128, HH, BB), 256, ATT_SMEM>>>(Out);
}